// round 9
// baseline (speedup 1.0000x reference)
#include <cuda_runtime.h>
#include <cuda_fp16.h>
#include <cstdint>

#define NN   50000
#define EE   800000
#define FIN  128
#define D0   256
#define DIMV 64
#define GG   256
#define OUTW 320   // D0 + DIMV

// ---------------- scratch (device globals; no allocation) ----------------
__device__ float  g_q[NN * D0];
__device__ __half g_kh[NN * D0];
__device__ __half g_vh[NN * D0];
__device__ float  g_o[NN * D0];
__device__ __half g_xh[NN * FIN];
__device__ __half g_hh[NN * D0];
__device__ int    g_deg[NN];
__device__ int    g_offs[NN];
__device__ int    g_csrc[EE];
__device__ float  g_ca[EE];
__device__ float  g_statsA[2 * D0];
__device__ float  g_statsB[2 * DIMV];
__device__ float  g_cnt[GG];
__device__ __half g_Wph0[FIN * 4 * D0];
__device__ float  g_bp0[4 * D0];
__device__ __half g_Wph1[D0 * 4 * DIMV];
__device__ float  g_bp1[4 * DIMV];

// ---------------- helpers ----------------
__device__ __forceinline__ void red_add_v4(float* ptr, float4 v) {
    asm volatile("red.global.add.v4.f32 [%0], {%1,%2,%3,%4};"
                 :: "l"(ptr), "f"(v.x), "f"(v.y), "f"(v.z), "f"(v.w) : "memory");
}
__device__ __forceinline__ uint32_t smem_u32(const void* p) {
    return (uint32_t)__cvta_generic_to_shared(p);
}
__device__ __forceinline__ void cp_async16(uint32_t dst, const void* src, int src_sz) {
    asm volatile("cp.async.cg.shared.global [%0], [%1], 16, %2;"
                 :: "r"(dst), "l"(src), "r"(src_sz));
}
__device__ __forceinline__ void cp_commit() {
    asm volatile("cp.async.commit_group;");
}
__device__ __forceinline__ void ldsm_x4(uint32_t& r0, uint32_t& r1, uint32_t& r2,
                                        uint32_t& r3, uint32_t addr) {
    asm volatile("ldmatrix.sync.aligned.m8n8.x4.shared.b16 {%0,%1,%2,%3}, [%4];"
                 : "=r"(r0), "=r"(r1), "=r"(r2), "=r"(r3) : "r"(addr));
}
__device__ __forceinline__ void ldsm_x4_t(uint32_t& r0, uint32_t& r1, uint32_t& r2,
                                          uint32_t& r3, uint32_t addr) {
    asm volatile("ldmatrix.sync.aligned.m8n8.x4.trans.shared.b16 {%0,%1,%2,%3}, [%4];"
                 : "=r"(r0), "=r"(r1), "=r"(r2), "=r"(r3) : "r"(addr));
}
__device__ __forceinline__ void mma_f16(float& c0, float& c1, float& c2, float& c3,
                                        uint32_t a0, uint32_t a1, uint32_t a2, uint32_t a3,
                                        uint32_t b0, uint32_t b1) {
    asm volatile("mma.sync.aligned.m16n8k16.row.col.f32.f16.f16.f32 "
                 "{%0,%1,%2,%3}, {%4,%5,%6,%7}, {%8,%9}, {%0,%1,%2,%3};"
                 : "+f"(c0), "+f"(c1), "+f"(c2), "+f"(c3)
                 : "r"(a0), "r"(a1), "r"(a2), "r"(a3), "r"(b0), "r"(b1));
}

// ---------------- prep: zeroing + fp16 weight packing + x conversion ---------
__global__ void prep(float* pool, float* cnt, int* deg, float* statsA, float* statsB,
                     const float* __restrict__ x, __half* xh,
                     const float* __restrict__ Wq0, const float* __restrict__ Wk0,
                     const float* __restrict__ Wv0, const float* __restrict__ Ws0,
                     const float* __restrict__ bq0, const float* __restrict__ bk0,
                     const float* __restrict__ bv0, const float* __restrict__ bs0,
                     const float* __restrict__ Wq1, const float* __restrict__ Wk1,
                     const float* __restrict__ Wv1, const float* __restrict__ Ws1,
                     const float* __restrict__ bq1, const float* __restrict__ bk1,
                     const float* __restrict__ bv1, const float* __restrict__ bs1,
                     __half* Wph0, float* bp0, __half* Wph1, float* bp1) {
    int gs = gridDim.x * blockDim.x;
    int i0 = blockIdx.x * blockDim.x + threadIdx.x;
    for (int i = i0; i < GG * OUTW; i += gs) pool[i] = 0.f;
    for (int i = i0; i < GG; i += gs) cnt[i] = 0.f;
    for (int i = i0; i < NN; i += gs) deg[i] = 0;
    for (int i = i0; i < 2 * D0; i += gs) statsA[i] = 0.f;
    for (int i = i0; i < 2 * DIMV; i += gs) statsB[i] = 0.f;
    for (int i = i0; i < NN * FIN / 2; i += gs) {
        float2 v = *(const float2*)&x[i * 2];
        *(__half2*)&xh[i * 2] = __floats2half2_rn(v.x, v.y);
    }
    for (int i = i0; i < FIN * 4 * D0; i += gs) {
        int kk = i / (4 * D0), c = i % (4 * D0);
        int sel = c / D0, cc = c % D0;
        const float* W = sel == 0 ? Wq0 : sel == 1 ? Wk0 : sel == 2 ? Wv0 : Ws0;
        Wph0[i] = __float2half_rn(W[kk * D0 + cc]);
    }
    for (int i = i0; i < 4 * D0; i += gs) {
        int sel = i / D0, cc = i % D0;
        const float* b = sel == 0 ? bq0 : sel == 1 ? bk0 : sel == 2 ? bv0 : bs0;
        bp0[i] = b[cc];
    }
    for (int i = i0; i < D0 * 4 * DIMV; i += gs) {
        int kk = i / (4 * DIMV), c = i % (4 * DIMV);
        int sel = c / DIMV, cc = c % DIMV;
        const float* W = sel == 0 ? Wq1 : sel == 1 ? Wk1 : sel == 2 ? Wv1 : Ws1;
        Wph1[i] = __float2half_rn(W[kk * DIMV + cc]);
    }
    for (int i = i0; i < 4 * DIMV; i += gs) {
        int sel = i / DIMV, cc = i % DIMV;
        const float* b = sel == 0 ? bq1 : sel == 1 ? bk1 : sel == 2 ? bv1 : bs1;
        bp1[i] = b[cc];
    }
}

// ---------------- CSR build --------------------------------------------------
__global__ void hist_count(const int* __restrict__ ei, int* deg,
                           const int* __restrict__ batch, float* cnt) {
    int i = blockIdx.x * blockDim.x + threadIdx.x;
    if (i < EE) atomicAdd(&deg[ei[EE + i]], 1);
    if (i < NN) atomicAdd(&cnt[batch[i]], 1.f);
}

__global__ void scan_kernel(int* deg, int* offs) {   // 1 block, 1024 threads
    __shared__ int ps[1024];
    int t = threadIdx.x;
    const int CH = (NN + 1023) / 1024;
    int base = t * CH;
    int sum = 0;
    for (int i = 0; i < CH; i++) {
        int idx = base + i;
        if (idx < NN) sum += deg[idx];
    }
    ps[t] = sum;
    __syncthreads();
    for (int off = 1; off < 1024; off <<= 1) {
        int v = (t >= off) ? ps[t - off] : 0;
        __syncthreads();
        ps[t] += v;
        __syncthreads();
    }
    int run = (t > 0) ? ps[t - 1] : 0;
    for (int i = 0; i < CH; i++) {
        int idx = base + i;
        if (idx < NN) {
            offs[idx] = run;
            run += deg[idx];
            deg[idx] = 0;
        }
    }
}

__global__ void fill_csr(const int* __restrict__ ei, const float* __restrict__ ea,
                         const int* __restrict__ offs, int* deg,
                         int* csrc, float* ca) {
    int e = blockIdx.x * blockDim.x + threadIdx.x;
    if (e >= EE) return;
    int dst = ei[EE + e];
    int slot = offs[dst] + atomicAdd(&deg[dst], 1);
    csrc[slot] = ei[e];
    ca[slot] = ea[e];
}

// ---------------- fp16 tensor-core GEMM, cp.async double-buffered ------------
#define BM 128
#define BN 128
#define BKH 32
#define APITCH 40
#define BPITCH 136

__global__ __launch_bounds__(256)
void hgemm4(const __half* __restrict__ A, const __half* __restrict__ Wp,
            const float* __restrict__ bp,
            float* __restrict__ Oq, __half* __restrict__ Ok,
            __half* __restrict__ Ov, float* __restrict__ Oo,
            int M, int K, int lda, int D) {
    const int Nc = 4 * D;
    __shared__ __half As[2][BM][APITCH];
    __shared__ __half Bs[2][BKH][BPITCH];

    int t = threadIdx.x;
    int lane = t & 31;
    int warp = t >> 5;
    int wm = warp >> 2;
    int wn = warp & 3;
    int g = lane >> 2;
    int t4 = lane & 3;
    int row0 = blockIdx.y * BM;
    int col0 = blockIdx.x * BN;

    float acc[4][4][4] = {};

    int a_r0 = t >> 2, a_c0 = (t & 3) * 8;
    int a_r1 = (t + 256) >> 2, a_c1 = ((t + 256) & 3) * 8;
    int b_r0 = t >> 4, b_c0 = (t & 15) * 8;
    int b_r1 = (t + 256) >> 4, b_c1 = ((t + 256) & 15) * 8;

    int a_row_l = lane & 15;
    int a_koff = (lane >> 4) * 8;
    int b_krow_l = ((lane >> 3) & 1) * 8 + (lane & 7);
    int b_noff = (lane >> 4) * 8;

    const int KT = K / BKH;

    auto load_tiles = [&](int st, int k0) {
        int gr0 = row0 + a_r0, gr1 = row0 + a_r1;
        cp_async16(smem_u32(&As[st][a_r0][a_c0]), &A[gr0 * lda + k0 + a_c0],
                   gr0 < M ? 16 : 0);
        cp_async16(smem_u32(&As[st][a_r1][a_c1]), &A[gr1 * lda + k0 + a_c1],
                   gr1 < M ? 16 : 0);
        cp_async16(smem_u32(&Bs[st][b_r0][b_c0]), &Wp[(k0 + b_r0) * Nc + col0 + b_c0], 16);
        cp_async16(smem_u32(&Bs[st][b_r1][b_c1]), &Wp[(k0 + b_r1) * Nc + col0 + b_c1], 16);
    };

    load_tiles(0, 0);
    cp_commit();

    for (int kt = 0; kt < KT; kt++) {
        int st = kt & 1;
        if (kt + 1 < KT) {
            load_tiles(st ^ 1, (kt + 1) * BKH);
            cp_commit();
            asm volatile("cp.async.wait_group 1;");
        } else {
            asm volatile("cp.async.wait_group 0;");
        }
        __syncthreads();

        #pragma unroll
        for (int ks = 0; ks < 2; ks++) {
            int kk = ks * 16;
            uint32_t af[4][4], bf[4][2];
            #pragma unroll
            for (int mt = 0; mt < 4; mt++) {
                int rb = wm * 64 + mt * 16;
                uint32_t addr = smem_u32(&As[st][rb + a_row_l][kk + a_koff]);
                ldsm_x4(af[mt][0], af[mt][1], af[mt][2], af[mt][3], addr);
            }
            #pragma unroll
            for (int p = 0; p < 2; p++) {
                int n0 = wn * 32 + p * 16;
                uint32_t addr = smem_u32(&Bs[st][kk + b_krow_l][n0 + b_noff]);
                ldsm_x4_t(bf[2 * p][0], bf[2 * p][1], bf[2 * p + 1][0], bf[2 * p + 1][1],
                          addr);
            }
            #pragma unroll
            for (int mt = 0; mt < 4; mt++)
                #pragma unroll
                for (int nt = 0; nt < 4; nt++)
                    mma_f16(acc[mt][nt][0], acc[mt][nt][1], acc[mt][nt][2], acc[mt][nt][3],
                            af[mt][0], af[mt][1], af[mt][2], af[mt][3],
                            bf[nt][0], bf[nt][1]);
        }
        __syncthreads();
    }

    #pragma unroll
    for (int nt = 0; nt < 4; nt++) {
        int cg = col0 + wn * 32 + nt * 8;
        int sel = cg / D;
        int cc = cg % D;
        int c0 = cc + 2 * t4;
        float2 bias = *(const float2*)&bp[cg + 2 * t4];
        if (sel == 1 || sel == 2) {
            __half* O = (sel == 1) ? Ok : Ov;
            #pragma unroll
            for (int mt = 0; mt < 4; mt++) {
                int r0 = row0 + wm * 64 + mt * 16 + g;
                if (r0 < M)
                    *(__half2*)&O[r0 * D + c0] =
                        __floats2half2_rn(acc[mt][nt][0] + bias.x, acc[mt][nt][1] + bias.y);
                if (r0 + 8 < M)
                    *(__half2*)&O[(r0 + 8) * D + c0] =
                        __floats2half2_rn(acc[mt][nt][2] + bias.x, acc[mt][nt][3] + bias.y);
            }
        } else {
            float* O = (sel == 0) ? Oq : Oo;
            #pragma unroll
            for (int mt = 0; mt < 4; mt++) {
                int r0 = row0 + wm * 64 + mt * 16 + g;
                if (r0 < M)
                    *(float2*)&O[r0 * D + c0] =
                        make_float2(acc[mt][nt][0] + bias.x, acc[mt][nt][1] + bias.y);
                if (r0 + 8 < M)
                    *(float2*)&O[(r0 + 8) * D + c0] =
                        make_float2(acc[mt][nt][2] + bias.x, acc[mt][nt][3] + bias.y);
            }
        }
    }
}

// ---------------- node aggregation: two-phase chunked, low-register ----------
// warp per node; lane owns D/32 contiguous cols. Per 32-edge chunk:
//   phase A: gather k rows only, compute p = exp((q·k + a·q·We)·scale) -> smem
//   phase B: gather v rows only, acc += p·v
// Keeps only packed uint4 rows live -> low regs -> 3 blocks/SM.
template <int D>
__device__ __forceinline__ float dot_packed(uint4 u, const float* qr) {
    float d = 0.f;
    float2 f;
    f = __half22float2(*(__half2*)&u.x); d = fmaf(qr[0], f.x, d); d = fmaf(qr[1], f.y, d);
    f = __half22float2(*(__half2*)&u.y); d = fmaf(qr[2], f.x, d); d = fmaf(qr[3], f.y, d);
    f = __half22float2(*(__half2*)&u.z); d = fmaf(qr[4], f.x, d); d = fmaf(qr[5], f.y, d);
    f = __half22float2(*(__half2*)&u.w); d = fmaf(qr[6], f.x, d); d = fmaf(qr[7], f.y, d);
    return d;
}
__device__ __forceinline__ void acc_packed(uint4 u, float p, float* acc) {
    float2 f;
    f = __half22float2(*(__half2*)&u.x); acc[0] = fmaf(p, f.x, acc[0]); acc[1] = fmaf(p, f.y, acc[1]);
    f = __half22float2(*(__half2*)&u.y); acc[2] = fmaf(p, f.x, acc[2]); acc[3] = fmaf(p, f.y, acc[3]);
    f = __half22float2(*(__half2*)&u.z); acc[4] = fmaf(p, f.x, acc[4]); acc[5] = fmaf(p, f.y, acc[5]);
    f = __half22float2(*(__half2*)&u.w); acc[6] = fmaf(p, f.x, acc[6]); acc[7] = fmaf(p, f.y, acc[7]);
}

template <int D>
__global__ __launch_bounds__(256, 3)
void node_agg(const float* __restrict__ q, const __half* __restrict__ kh,
              const __half* __restrict__ vh, float* __restrict__ o,
              const int* __restrict__ offs, const int* __restrict__ deg,
              const int* __restrict__ csrc, const float* __restrict__ ca,
              const float* __restrict__ We, float* __restrict__ stats, float scale) {
    constexpr int C = D / 32;      // 8 for D0, 2 for DIMV
    constexpr int CH = 32;         // edges per chunk
    __shared__ float ssu[D], ssq[D];
    __shared__ float pbuf[8][CH];
    int t = threadIdx.x, lane = t & 31, w = t >> 5;
    for (int i = t; i < D; i += 256) { ssu[i] = 0.f; ssq[i] = 0.f; }
    __syncthreads();
    int c0 = lane * C;
    float su[C] = {}, sq[C] = {};
    int wg = blockIdx.x * 8 + w, tw = gridDim.x * 8;

    for (int n = wg; n < NN; n += tw) {
        float qr[C];
        if constexpr (D == 256) {
            float4 a0 = *(const float4*)&q[n * D + c0];
            float4 a1 = *(const float4*)&q[n * D + c0 + 4];
            qr[0] = a0.x; qr[1] = a0.y; qr[2] = a0.z; qr[3] = a0.w;
            qr[4] = a1.x; qr[5] = a1.y; qr[6] = a1.z; qr[7] = a1.w;
        } else {
            float2 a0 = *(const float2*)&q[n * D + c0];
            qr[0] = a0.x; qr[1] = a0.y;
        }
        float qwe = 0.f;
        #pragma unroll
        for (int i = 0; i < C; i++) qwe += qr[i] * __ldg(&We[c0 + i]);
        #pragma unroll
        for (int off = 16; off > 0; off >>= 1)
            qwe += __shfl_xor_sync(0xffffffffu, qwe, off);

        float acc[C] = {};
        float s = 0.f, pa = 0.f;
        int jb = offs[n], dg = deg[n];

        for (int cb = 0; cb < dg; cb += CH) {
            int ce = min(dg - cb, CH);
            int base = jb + cb;
            // ---- phase A: k gathers -> p into smem ----
            int j = 0;
            for (; j + 4 <= ce; j += 4) {
                int b = base + j;
                int e0 = __ldg(&csrc[b]),     e1 = __ldg(&csrc[b + 1]);
                int e2 = __ldg(&csrc[b + 2]), e3 = __ldg(&csrc[b + 3]);
                float a0 = __ldg(&ca[b]),     a1 = __ldg(&ca[b + 1]);
                float a2 = __ldg(&ca[b + 2]), a3 = __ldg(&ca[b + 3]);
                float d0, d1, d2, d3;
                if constexpr (D == 256) {
                    uint4 u0 = *(const uint4*)&kh[e0 * D + c0];
                    uint4 u1 = *(const uint4*)&kh[e1 * D + c0];
                    uint4 u2 = *(const uint4*)&kh[e2 * D + c0];
                    uint4 u3 = *(const uint4*)&kh[e3 * D + c0];
                    d0 = dot_packed<D>(u0, qr); d1 = dot_packed<D>(u1, qr);
                    d2 = dot_packed<D>(u2, qr); d3 = dot_packed<D>(u3, qr);
                } else {
                    uint32_t u0 = *(const uint32_t*)&kh[e0 * D + c0];
                    uint32_t u1 = *(const uint32_t*)&kh[e1 * D + c0];
                    uint32_t u2 = *(const uint32_t*)&kh[e2 * D + c0];
                    uint32_t u3 = *(const uint32_t*)&kh[e3 * D + c0];
                    float2 f;
                    f = __half22float2(*(__half2*)&u0); d0 = qr[0] * f.x + qr[1] * f.y;
                    f = __half22float2(*(__half2*)&u1); d1 = qr[0] * f.x + qr[1] * f.y;
                    f = __half22float2(*(__half2*)&u2); d2 = qr[0] * f.x + qr[1] * f.y;
                    f = __half22float2(*(__half2*)&u3); d3 = qr[0] * f.x + qr[1] * f.y;
                }
                #pragma unroll
                for (int off = 16; off > 0; off >>= 1) {
                    d0 += __shfl_xor_sync(0xffffffffu, d0, off);
                    d1 += __shfl_xor_sync(0xffffffffu, d1, off);
                    d2 += __shfl_xor_sync(0xffffffffu, d2, off);
                    d3 += __shfl_xor_sync(0xffffffffu, d3, off);
                }
                float p0 = __expf((d0 + a0 * qwe) * scale);
                float p1 = __expf((d1 + a1 * qwe) * scale);
                float p2 = __expf((d2 + a2 * qwe) * scale);
                float p3 = __expf((d3 + a3 * qwe) * scale);
                s += (p0 + p1) + (p2 + p3);
                pa = fmaf(p0, a0, pa); pa = fmaf(p1, a1, pa);
                pa = fmaf(p2, a2, pa); pa = fmaf(p3, a3, pa);
                if (lane == 0) {
                    pbuf[w][j] = p0; pbuf[w][j + 1] = p1;
                    pbuf[w][j + 2] = p2; pbuf[w][j + 3] = p3;
                }
            }
            for (; j < ce; j++) {
                int b = base + j;
                int e0 = __ldg(&csrc[b]);
                float a0 = __ldg(&ca[b]);
                float d0;
                if constexpr (D == 256) {
                    uint4 u0 = *(const uint4*)&kh[e0 * D + c0];
                    d0 = dot_packed<D>(u0, qr);
                } else {
                    uint32_t u0 = *(const uint32_t*)&kh[e0 * D + c0];
                    float2 f = __half22float2(*(__half2*)&u0);
                    d0 = qr[0] * f.x + qr[1] * f.y;
                }
                #pragma unroll
                for (int off = 16; off > 0; off >>= 1)
                    d0 += __shfl_xor_sync(0xffffffffu, d0, off);
                float p0 = __expf((d0 + a0 * qwe) * scale);
                s += p0;
                pa = fmaf(p0, a0, pa);
                if (lane == 0) pbuf[w][j] = p0;
            }
            __syncwarp();
            // ---- phase B: v gathers, weighted accumulate ----
            j = 0;
            for (; j + 4 <= ce; j += 4) {
                int b = base + j;
                int e0 = __ldg(&csrc[b]),     e1 = __ldg(&csrc[b + 1]);
                int e2 = __ldg(&csrc[b + 2]), e3 = __ldg(&csrc[b + 3]);
                float p0 = pbuf[w][j],     p1 = pbuf[w][j + 1];
                float p2 = pbuf[w][j + 2], p3 = pbuf[w][j + 3];
                if constexpr (D == 256) {
                    uint4 u0 = *(const uint4*)&vh[e0 * D + c0];
                    uint4 u1 = *(const uint4*)&vh[e1 * D + c0];
                    uint4 u2 = *(const uint4*)&vh[e2 * D + c0];
                    uint4 u3 = *(const uint4*)&vh[e3 * D + c0];
                    acc_packed(u0, p0, acc); acc_packed(u1, p1, acc);
                    acc_packed(u2, p2, acc); acc_packed(u3, p3, acc);
                } else {
                    uint32_t u0 = *(const uint32_t*)&vh[e0 * D + c0];
                    uint32_t u1 = *(const uint32_t*)&vh[e1 * D + c0];
                    uint32_t u2 = *(const uint32_t*)&vh[e2 * D + c0];
                    uint32_t u3 = *(const uint32_t*)&vh[e3 * D + c0];
                    float2 f;
                    f = __half22float2(*(__half2*)&u0); acc[0] = fmaf(p0, f.x, acc[0]); acc[1] = fmaf(p0, f.y, acc[1]);
                    f = __half22float2(*(__half2*)&u1); acc[0] = fmaf(p1, f.x, acc[0]); acc[1] = fmaf(p1, f.y, acc[1]);
                    f = __half22float2(*(__half2*)&u2); acc[0] = fmaf(p2, f.x, acc[0]); acc[1] = fmaf(p2, f.y, acc[1]);
                    f = __half22float2(*(__half2*)&u3); acc[0] = fmaf(p3, f.x, acc[0]); acc[1] = fmaf(p3, f.y, acc[1]);
                }
            }
            for (; j < ce; j++) {
                int b = base + j;
                int e0 = __ldg(&csrc[b]);
                float p0 = pbuf[w][j];
                if constexpr (D == 256) {
                    uint4 u0 = *(const uint4*)&vh[e0 * D + c0];
                    acc_packed(u0, p0, acc);
                } else {
                    uint32_t u0 = *(const uint32_t*)&vh[e0 * D + c0];
                    float2 f = __half22float2(*(__half2*)&u0);
                    acc[0] = fmaf(p0, f.x, acc[0]); acc[1] = fmaf(p0, f.y, acc[1]);
                }
            }
            __syncwarp();
        }

        float inv = 1.f / (s + 1e-16f);
        float val[C];
        if constexpr (D == 256) {
            float4 s0 = *(const float4*)&o[n * D + c0];
            float4 s1 = *(const float4*)&o[n * D + c0 + 4];
            float sk[8] = {s0.x, s0.y, s0.z, s0.w, s1.x, s1.y, s1.z, s1.w};
            #pragma unroll
            for (int i = 0; i < 8; i++)
                val[i] = sk[i] + (acc[i] + pa * __ldg(&We[c0 + i])) * inv;
            *(float4*)&o[n * D + c0] = make_float4(val[0], val[1], val[2], val[3]);
            *(float4*)&o[n * D + c0 + 4] = make_float4(val[4], val[5], val[6], val[7]);
        } else {
            float2 s0 = *(const float2*)&o[n * D + c0];
            val[0] = s0.x + (acc[0] + pa * __ldg(&We[c0])) * inv;
            val[1] = s0.y + (acc[1] + pa * __ldg(&We[c0 + 1])) * inv;
            *(float2*)&o[n * D + c0] = make_float2(val[0], val[1]);
        }
        #pragma unroll
        for (int i = 0; i < C; i++) { su[i] += val[i]; sq[i] += val[i] * val[i]; }
    }

    #pragma unroll
    for (int i = 0; i < C; i++) {
        atomicAdd(&ssu[c0 + i], su[i]);
        atomicAdd(&ssq[c0 + i], sq[i]);
    }
    __syncthreads();
    for (int i = t; i < D; i += 256) {
        atomicAdd(&stats[i], ssu[i]);
        atomicAdd(&stats[D + i], ssq[i]);
    }
}

// ---------------- batch norm apply (finalize folded in) ----------------------
template <int D>
__global__ void bn_apply(const float* __restrict__ X, const float* __restrict__ stats,
                         const float* __restrict__ gamma, const float* __restrict__ beta,
                         float* __restrict__ xs, __half* __restrict__ hh,
                         float* __restrict__ pool, const int* __restrict__ batch,
                         int col_off) {
    constexpr int CG = D / 4;
    constexpr int RL = 256 / CG;
    constexpr int CHUNK = 16;
    int t = threadIdx.x;
    int cg = t % CG, rl = t / CG;
    int r0 = blockIdx.x * (RL * CHUNK) + rl * CHUNK;
    int c4 = cg * 4;
    const float invN = 1.f / (float)NN;
    float4 suv = *(const float4*)&stats[c4];
    float4 sqv = *(const float4*)&stats[D + c4];
    float4 mu, rs;
    mu.x = suv.x * invN; mu.y = suv.y * invN; mu.z = suv.z * invN; mu.w = suv.w * invN;
    rs.x = rsqrtf(sqv.x * invN - mu.x * mu.x + 1e-5f);
    rs.y = rsqrtf(sqv.y * invN - mu.y * mu.y + 1e-5f);
    rs.z = rsqrtf(sqv.z * invN - mu.z * mu.z + 1e-5f);
    rs.w = rsqrtf(sqv.w * invN - mu.w * mu.w + 1e-5f);
    float4 gm = *(const float4*)&gamma[c4];
    float4 bt = *(const float4*)&beta[c4];
    float4 acc = make_float4(0.f, 0.f, 0.f, 0.f);
    int curb = -1;
    for (int i = 0; i < CHUNK; i++) {
        int r = r0 + i;
        if (r >= NN) break;
        int b = __ldg(&batch[r]);
        if (b != curb) {
            if (curb >= 0) red_add_v4(&pool[curb * OUTW + col_off + c4], acc);
            acc = make_float4(0.f, 0.f, 0.f, 0.f);
            curb = b;
        }
        float4 xv = *(const float4*)&X[r * D + c4];
        float4 val;
        val.x = gm.x * (xv.x - mu.x) * rs.x + bt.x;
        val.y = gm.y * (xv.y - mu.y) * rs.y + bt.y;
        val.z = gm.z * (xv.z - mu.z) * rs.z + bt.z;
        val.w = gm.w * (xv.w - mu.w) * rs.w + bt.w;
        *(float4*)&xs[r * OUTW + col_off + c4] = val;
        if (hh) {
            __half2 h0 = __floats2half2_rn(val.x, val.y);
            __half2 h1 = __floats2half2_rn(val.z, val.w);
            *(uint2*)&hh[r * D + c4] = make_uint2(*(uint32_t*)&h0, *(uint32_t*)&h1);
        }
        acc.x += val.x; acc.y += val.y; acc.z += val.z; acc.w += val.w;
    }
    if (curb >= 0) red_add_v4(&pool[curb * OUTW + col_off + c4], acc);
}

__global__ void pool_div(float* pool, const float* __restrict__ cnt) {
    int i = blockIdx.x * blockDim.x + threadIdx.x;
    if (i >= GG * OUTW) return;
    pool[i] /= fmaxf(cnt[i / OUTW], 1.f);
}

// ---------------- launch -----------------------------------------------------
extern "C" void kernel_launch(void* const* d_in, const int* in_sizes, int n_in,
                              void* d_out, int out_size) {
    const float* x     = (const float*)d_in[0];
    const int*   ei    = (const int*)  d_in[1];
    const float* ea    = (const float*)d_in[2];
    const int*   batch = (const int*)  d_in[3];
    const float* Wq0 = (const float*)d_in[4];  const float* bq0 = (const float*)d_in[5];
    const float* Wk0 = (const float*)d_in[6];  const float* bk0 = (const float*)d_in[7];
    const float* Wv0 = (const float*)d_in[8];  const float* bv0 = (const float*)d_in[9];
    const float* We0 = (const float*)d_in[10];
    const float* Ws0 = (const float*)d_in[11]; const float* bs0 = (const float*)d_in[12];
    const float* gamma0 = (const float*)d_in[13]; const float* beta0 = (const float*)d_in[14];
    const float* Wq1 = (const float*)d_in[15]; const float* bq1 = (const float*)d_in[16];
    const float* Wk1 = (const float*)d_in[17]; const float* bk1 = (const float*)d_in[18];
    const float* Wv1 = (const float*)d_in[19]; const float* bv1 = (const float*)d_in[20];
    const float* We1 = (const float*)d_in[21];
    const float* Ws1 = (const float*)d_in[22]; const float* bs1 = (const float*)d_in[23];
    const float* gamma1 = (const float*)d_in[24]; const float* beta1 = (const float*)d_in[25];

    float* out  = (float*)d_out;
    float* pool = out;
    float* xs   = out + GG * OUTW;

    float *q, *o, *statsA, *statsB, *cnt, *bp0, *bp1, *ca;
    __half *kh, *vh, *xh, *hh, *Wph0, *Wph1;
    int *deg, *offs, *csrc;
    cudaGetSymbolAddress((void**)&q, g_q);
    cudaGetSymbolAddress((void**)&kh, g_kh);
    cudaGetSymbolAddress((void**)&vh, g_vh);
    cudaGetSymbolAddress((void**)&o, g_o);
    cudaGetSymbolAddress((void**)&xh, g_xh);
    cudaGetSymbolAddress((void**)&hh, g_hh);
    cudaGetSymbolAddress((void**)&deg, g_deg);
    cudaGetSymbolAddress((void**)&offs, g_offs);
    cudaGetSymbolAddress((void**)&csrc, g_csrc);
    cudaGetSymbolAddress((void**)&ca, g_ca);
    cudaGetSymbolAddress((void**)&statsA, g_statsA);
    cudaGetSymbolAddress((void**)&statsB, g_statsB);
    cudaGetSymbolAddress((void**)&cnt, g_cnt);
    cudaGetSymbolAddress((void**)&Wph0, g_Wph0);
    cudaGetSymbolAddress((void**)&bp0, g_bp0);
    cudaGetSymbolAddress((void**)&Wph1, g_Wph1);
    cudaGetSymbolAddress((void**)&bp1, g_bp1);

    const int TB = 256;

    // 0: prep   1: hist   2: scan   3: gemm L0 (profiled slot)   4: fill_csr
    prep<<<512, TB>>>(pool, cnt, deg, statsA, statsB, x, xh,
                      Wq0, Wk0, Wv0, Ws0, bq0, bk0, bv0, bs0,
                      Wq1, Wk1, Wv1, Ws1, bq1, bk1, bv1, bs1,
                      Wph0, bp0, Wph1, bp1);
    hist_count<<<(EE + TB - 1) / TB, TB>>>(ei, deg, batch, cnt);
    scan_kernel<<<1, 1024>>>(deg, offs);

    dim3 g0(4 * D0 / BN, (NN + BM - 1) / BM);
    hgemm4<<<g0, 256>>>(xh, Wph0, bp0, q, kh, vh, o, NN, FIN, FIN, D0);

    fill_csr<<<(EE + TB - 1) / TB, TB>>>(ei, ea, offs, deg, csrc, ca);

    node_agg<D0><<<1184, 256>>>(q, kh, vh, o, offs, deg, csrc, ca, We0, statsA, 1.f / 16.f);

    bn_apply<D0><<<(NN + 63) / 64, 256>>>(o, statsA, gamma0, beta0, xs, hh, pool, batch, 0);

    dim3 g1(4 * DIMV / BN, (NN + BM - 1) / BM);
    hgemm4<<<g1, 256>>>(hh, Wph1, bp1, q, kh, vh, o, NN, D0, D0, DIMV);

    node_agg<DIMV><<<1184, 256>>>(q, kh, vh, o, offs, deg, csrc, ca, We1, statsB, 1.f / 8.f);

    bn_apply<DIMV><<<(NN + 255) / 256, 256>>>(o, statsB, gamma1, beta1, xs, nullptr, pool,
                                              batch, D0);

    pool_div<<<(GG * OUTW + TB - 1) / TB, TB>>>(pool, cnt);
}

// round 10
// speedup vs baseline: 1.0988x; 1.0988x over previous
#include <cuda_runtime.h>
#include <cuda_fp16.h>
#include <cstdint>

#define NN   50000
#define EE   800000
#define FIN  128
#define D0   256
#define DIMV 64
#define GG   256
#define OUTW 320   // D0 + DIMV

// ---------------- scratch (device globals; no allocation) ----------------
__device__ float  g_q[NN * D0];
__device__ __half g_kh[NN * D0];
__device__ __half g_vh[NN * D0];
__device__ float  g_o[NN * D0];
__device__ __half g_xh[NN * FIN];
__device__ __half g_hh[NN * D0];
__device__ int    g_deg[NN];
__device__ int    g_offs[NN];
__device__ int    g_csrc[EE];
__device__ float  g_ca[EE];
__device__ float  g_statsA[2 * D0];
__device__ float  g_statsB[2 * DIMV];
__device__ float  g_cnt[GG];
__device__ __half g_Wph0[FIN * 4 * D0];
__device__ float  g_bp0[4 * D0];
__device__ __half g_Wph1[D0 * 4 * DIMV];
__device__ float  g_bp1[4 * DIMV];

// ---------------- helpers ----------------
__device__ __forceinline__ void red_add_v4(float* ptr, float4 v) {
    asm volatile("red.global.add.v4.f32 [%0], {%1,%2,%3,%4};"
                 :: "l"(ptr), "f"(v.x), "f"(v.y), "f"(v.z), "f"(v.w) : "memory");
}
__device__ __forceinline__ uint32_t smem_u32(const void* p) {
    return (uint32_t)__cvta_generic_to_shared(p);
}
__device__ __forceinline__ void cp_async16(uint32_t dst, const void* src, int src_sz) {
    asm volatile("cp.async.cg.shared.global [%0], [%1], 16, %2;"
                 :: "r"(dst), "l"(src), "r"(src_sz));
}
__device__ __forceinline__ void cp_commit() {
    asm volatile("cp.async.commit_group;");
}
__device__ __forceinline__ void ldsm_x4(uint32_t& r0, uint32_t& r1, uint32_t& r2,
                                        uint32_t& r3, uint32_t addr) {
    asm volatile("ldmatrix.sync.aligned.m8n8.x4.shared.b16 {%0,%1,%2,%3}, [%4];"
                 : "=r"(r0), "=r"(r1), "=r"(r2), "=r"(r3) : "r"(addr));
}
__device__ __forceinline__ void ldsm_x4_t(uint32_t& r0, uint32_t& r1, uint32_t& r2,
                                          uint32_t& r3, uint32_t addr) {
    asm volatile("ldmatrix.sync.aligned.m8n8.x4.trans.shared.b16 {%0,%1,%2,%3}, [%4];"
                 : "=r"(r0), "=r"(r1), "=r"(r2), "=r"(r3) : "r"(addr));
}
__device__ __forceinline__ void mma_f16(float& c0, float& c1, float& c2, float& c3,
                                        uint32_t a0, uint32_t a1, uint32_t a2, uint32_t a3,
                                        uint32_t b0, uint32_t b1) {
    asm volatile("mma.sync.aligned.m16n8k16.row.col.f32.f16.f16.f32 "
                 "{%0,%1,%2,%3}, {%4,%5,%6,%7}, {%8,%9}, {%0,%1,%2,%3};"
                 : "+f"(c0), "+f"(c1), "+f"(c2), "+f"(c3)
                 : "r"(a0), "r"(a1), "r"(a2), "r"(a3), "r"(b0), "r"(b1));
}

// ---------------- prep: zeroing + fp16 weight packing + x conversion ---------
__global__ void prep(float* pool, float* cnt, int* deg, float* statsA, float* statsB,
                     const float* __restrict__ x, __half* xh,
                     const float* __restrict__ Wq0, const float* __restrict__ Wk0,
                     const float* __restrict__ Wv0, const float* __restrict__ Ws0,
                     const float* __restrict__ bq0, const float* __restrict__ bk0,
                     const float* __restrict__ bv0, const float* __restrict__ bs0,
                     const float* __restrict__ Wq1, const float* __restrict__ Wk1,
                     const float* __restrict__ Wv1, const float* __restrict__ Ws1,
                     const float* __restrict__ bq1, const float* __restrict__ bk1,
                     const float* __restrict__ bv1, const float* __restrict__ bs1,
                     __half* Wph0, float* bp0, __half* Wph1, float* bp1) {
    int gs = gridDim.x * blockDim.x;
    int i0 = blockIdx.x * blockDim.x + threadIdx.x;
    for (int i = i0; i < GG * OUTW; i += gs) pool[i] = 0.f;
    for (int i = i0; i < GG; i += gs) cnt[i] = 0.f;
    for (int i = i0; i < NN; i += gs) deg[i] = 0;
    for (int i = i0; i < 2 * D0; i += gs) statsA[i] = 0.f;
    for (int i = i0; i < 2 * DIMV; i += gs) statsB[i] = 0.f;
    for (int i = i0; i < NN * FIN / 2; i += gs) {
        float2 v = *(const float2*)&x[i * 2];
        *(__half2*)&xh[i * 2] = __floats2half2_rn(v.x, v.y);
    }
    for (int i = i0; i < FIN * 4 * D0; i += gs) {
        int kk = i / (4 * D0), c = i % (4 * D0);
        int sel = c / D0, cc = c % D0;
        const float* W = sel == 0 ? Wq0 : sel == 1 ? Wk0 : sel == 2 ? Wv0 : Ws0;
        Wph0[i] = __float2half_rn(W[kk * D0 + cc]);
    }
    for (int i = i0; i < 4 * D0; i += gs) {
        int sel = i / D0, cc = i % D0;
        const float* b = sel == 0 ? bq0 : sel == 1 ? bk0 : sel == 2 ? bv0 : bs0;
        bp0[i] = b[cc];
    }
    for (int i = i0; i < D0 * 4 * DIMV; i += gs) {
        int kk = i / (4 * DIMV), c = i % (4 * DIMV);
        int sel = c / DIMV, cc = c % DIMV;
        const float* W = sel == 0 ? Wq1 : sel == 1 ? Wk1 : sel == 2 ? Wv1 : Ws1;
        Wph1[i] = __float2half_rn(W[kk * DIMV + cc]);
    }
    for (int i = i0; i < 4 * DIMV; i += gs) {
        int sel = i / DIMV, cc = i % DIMV;
        const float* b = sel == 0 ? bq1 : sel == 1 ? bk1 : sel == 2 ? bv1 : bs1;
        bp1[i] = b[cc];
    }
}

// ---------------- CSR build --------------------------------------------------
__global__ void hist_count(const int* __restrict__ ei, int* deg,
                           const int* __restrict__ batch, float* cnt) {
    int i = blockIdx.x * blockDim.x + threadIdx.x;
    if (i < EE) atomicAdd(&deg[ei[EE + i]], 1);
    if (i < NN) atomicAdd(&cnt[batch[i]], 1.f);
}

__global__ void scan_kernel(int* deg, int* offs) {   // 1 block, 1024 threads
    __shared__ int ps[1024];
    int t = threadIdx.x;
    const int CH = (NN + 1023) / 1024;
    int base = t * CH;
    int sum = 0;
    for (int i = 0; i < CH; i++) {
        int idx = base + i;
        if (idx < NN) sum += deg[idx];
    }
    ps[t] = sum;
    __syncthreads();
    for (int off = 1; off < 1024; off <<= 1) {
        int v = (t >= off) ? ps[t - off] : 0;
        __syncthreads();
        ps[t] += v;
        __syncthreads();
    }
    int run = (t > 0) ? ps[t - 1] : 0;
    for (int i = 0; i < CH; i++) {
        int idx = base + i;
        if (idx < NN) {
            offs[idx] = run;
            run += deg[idx];
            deg[idx] = 0;
        }
    }
}

__global__ void fill_csr(const int* __restrict__ ei, const float* __restrict__ ea,
                         const int* __restrict__ offs, int* deg,
                         int* csrc, float* ca) {
    int e = blockIdx.x * blockDim.x + threadIdx.x;
    if (e >= EE) return;
    int dst = ei[EE + e];
    int slot = offs[dst] + atomicAdd(&deg[dst], 1);
    csrc[slot] = ei[e];
    ca[slot] = ea[e];
}

// ---------------- fp16 tensor-core GEMM, cp.async double-buffered ------------
#define BM 128
#define BN 128
#define BKH 32
#define APITCH 40
#define BPITCH 136

__global__ __launch_bounds__(256)
void hgemm4(const __half* __restrict__ A, const __half* __restrict__ Wp,
            const float* __restrict__ bp,
            float* __restrict__ Oq, __half* __restrict__ Ok,
            __half* __restrict__ Ov, float* __restrict__ Oo,
            int M, int K, int lda, int D) {
    const int Nc = 4 * D;
    __shared__ __half As[2][BM][APITCH];
    __shared__ __half Bs[2][BKH][BPITCH];

    int t = threadIdx.x;
    int lane = t & 31;
    int warp = t >> 5;
    int wm = warp >> 2;
    int wn = warp & 3;
    int g = lane >> 2;
    int t4 = lane & 3;
    int row0 = blockIdx.y * BM;
    int col0 = blockIdx.x * BN;

    float acc[4][4][4] = {};

    int a_r0 = t >> 2, a_c0 = (t & 3) * 8;
    int a_r1 = (t + 256) >> 2, a_c1 = ((t + 256) & 3) * 8;
    int b_r0 = t >> 4, b_c0 = (t & 15) * 8;
    int b_r1 = (t + 256) >> 4, b_c1 = ((t + 256) & 15) * 8;

    int a_row_l = lane & 15;
    int a_koff = (lane >> 4) * 8;
    int b_krow_l = ((lane >> 3) & 1) * 8 + (lane & 7);
    int b_noff = (lane >> 4) * 8;

    const int KT = K / BKH;

    auto load_tiles = [&](int st, int k0) {
        int gr0 = row0 + a_r0, gr1 = row0 + a_r1;
        cp_async16(smem_u32(&As[st][a_r0][a_c0]), &A[gr0 * lda + k0 + a_c0],
                   gr0 < M ? 16 : 0);
        cp_async16(smem_u32(&As[st][a_r1][a_c1]), &A[gr1 * lda + k0 + a_c1],
                   gr1 < M ? 16 : 0);
        cp_async16(smem_u32(&Bs[st][b_r0][b_c0]), &Wp[(k0 + b_r0) * Nc + col0 + b_c0], 16);
        cp_async16(smem_u32(&Bs[st][b_r1][b_c1]), &Wp[(k0 + b_r1) * Nc + col0 + b_c1], 16);
    };

    load_tiles(0, 0);
    cp_commit();

    for (int kt = 0; kt < KT; kt++) {
        int st = kt & 1;
        if (kt + 1 < KT) {
            load_tiles(st ^ 1, (kt + 1) * BKH);
            cp_commit();
            asm volatile("cp.async.wait_group 1;");
        } else {
            asm volatile("cp.async.wait_group 0;");
        }
        __syncthreads();

        #pragma unroll
        for (int ks = 0; ks < 2; ks++) {
            int kk = ks * 16;
            uint32_t af[4][4], bf[4][2];
            #pragma unroll
            for (int mt = 0; mt < 4; mt++) {
                int rb = wm * 64 + mt * 16;
                uint32_t addr = smem_u32(&As[st][rb + a_row_l][kk + a_koff]);
                ldsm_x4(af[mt][0], af[mt][1], af[mt][2], af[mt][3], addr);
            }
            #pragma unroll
            for (int p = 0; p < 2; p++) {
                int n0 = wn * 32 + p * 16;
                uint32_t addr = smem_u32(&Bs[st][kk + b_krow_l][n0 + b_noff]);
                ldsm_x4_t(bf[2 * p][0], bf[2 * p][1], bf[2 * p + 1][0], bf[2 * p + 1][1],
                          addr);
            }
            #pragma unroll
            for (int mt = 0; mt < 4; mt++)
                #pragma unroll
                for (int nt = 0; nt < 4; nt++)
                    mma_f16(acc[mt][nt][0], acc[mt][nt][1], acc[mt][nt][2], acc[mt][nt][3],
                            af[mt][0], af[mt][1], af[mt][2], af[mt][3],
                            bf[nt][0], bf[nt][1]);
        }
        __syncthreads();
    }

    #pragma unroll
    for (int nt = 0; nt < 4; nt++) {
        int cg = col0 + wn * 32 + nt * 8;
        int sel = cg / D;
        int cc = cg % D;
        int c0 = cc + 2 * t4;
        float2 bias = *(const float2*)&bp[cg + 2 * t4];
        if (sel == 1 || sel == 2) {
            __half* O = (sel == 1) ? Ok : Ov;
            #pragma unroll
            for (int mt = 0; mt < 4; mt++) {
                int r0 = row0 + wm * 64 + mt * 16 + g;
                if (r0 < M)
                    *(__half2*)&O[r0 * D + c0] =
                        __floats2half2_rn(acc[mt][nt][0] + bias.x, acc[mt][nt][1] + bias.y);
                if (r0 + 8 < M)
                    *(__half2*)&O[(r0 + 8) * D + c0] =
                        __floats2half2_rn(acc[mt][nt][2] + bias.x, acc[mt][nt][3] + bias.y);
            }
        } else {
            float* O = (sel == 0) ? Oq : Oo;
            #pragma unroll
            for (int mt = 0; mt < 4; mt++) {
                int r0 = row0 + wm * 64 + mt * 16 + g;
                if (r0 < M)
                    *(float2*)&O[r0 * D + c0] =
                        make_float2(acc[mt][nt][0] + bias.x, acc[mt][nt][1] + bias.y);
                if (r0 + 8 < M)
                    *(float2*)&O[(r0 + 8) * D + c0] =
                        make_float2(acc[mt][nt][2] + bias.x, acc[mt][nt][3] + bias.y);
            }
        }
    }
}

// ---------------- node aggregation: single-phase, packed k/v, 4-edge ---------
// warp per node; lane owns D/32 contiguous cols. k/v stay packed (half2) in
// registers, converted inline -> low live-register footprint -> 3 CTAs/SM.
__device__ __forceinline__ float dot_packed8(uint4 u, const float* qr) {
    float d = 0.f;
    float2 f;
    f = __half22float2(*(__half2*)&u.x); d = fmaf(qr[0], f.x, d); d = fmaf(qr[1], f.y, d);
    f = __half22float2(*(__half2*)&u.y); d = fmaf(qr[2], f.x, d); d = fmaf(qr[3], f.y, d);
    f = __half22float2(*(__half2*)&u.z); d = fmaf(qr[4], f.x, d); d = fmaf(qr[5], f.y, d);
    f = __half22float2(*(__half2*)&u.w); d = fmaf(qr[6], f.x, d); d = fmaf(qr[7], f.y, d);
    return d;
}
__device__ __forceinline__ void acc_packed8(uint4 u, float p, float* acc) {
    float2 f;
    f = __half22float2(*(__half2*)&u.x); acc[0] = fmaf(p, f.x, acc[0]); acc[1] = fmaf(p, f.y, acc[1]);
    f = __half22float2(*(__half2*)&u.y); acc[2] = fmaf(p, f.x, acc[2]); acc[3] = fmaf(p, f.y, acc[3]);
    f = __half22float2(*(__half2*)&u.z); acc[4] = fmaf(p, f.x, acc[4]); acc[5] = fmaf(p, f.y, acc[5]);
    f = __half22float2(*(__half2*)&u.w); acc[6] = fmaf(p, f.x, acc[6]); acc[7] = fmaf(p, f.y, acc[7]);
}

template <int D>
__global__ __launch_bounds__(256, 3)
void node_agg(const float* __restrict__ q, const __half* __restrict__ kh,
              const __half* __restrict__ vh, float* __restrict__ o,
              const int* __restrict__ offs, const int* __restrict__ deg,
              const int* __restrict__ csrc, const float* __restrict__ ca,
              const float* __restrict__ We, float* __restrict__ stats, float scale) {
    constexpr int C = D / 32;      // 8 for D0, 2 for DIMV
    __shared__ float ssu[D], ssq[D];
    int t = threadIdx.x, lane = t & 31, w = t >> 5;
    for (int i = t; i < D; i += 256) { ssu[i] = 0.f; ssq[i] = 0.f; }
    __syncthreads();
    int c0 = lane * C;
    float su[C] = {}, sq[C] = {};
    int wg = blockIdx.x * 8 + w, tw = gridDim.x * 8;

    for (int n = wg; n < NN; n += tw) {
        float qr[C];
        if constexpr (D == 256) {
            float4 a0 = *(const float4*)&q[n * D + c0];
            float4 a1 = *(const float4*)&q[n * D + c0 + 4];
            qr[0] = a0.x; qr[1] = a0.y; qr[2] = a0.z; qr[3] = a0.w;
            qr[4] = a1.x; qr[5] = a1.y; qr[6] = a1.z; qr[7] = a1.w;
        } else {
            float2 a0 = *(const float2*)&q[n * D + c0];
            qr[0] = a0.x; qr[1] = a0.y;
        }
        float qwe = 0.f;
        #pragma unroll
        for (int i = 0; i < C; i++) qwe += qr[i] * __ldg(&We[c0 + i]);
        #pragma unroll
        for (int off = 16; off > 0; off >>= 1)
            qwe += __shfl_xor_sync(0xffffffffu, qwe, off);

        float acc[C] = {};
        float s = 0.f, pa = 0.f;
        int jb = offs[n], je = jb + deg[n];
        int j = jb;
        for (; j + 4 <= je; j += 4) {
            int e0 = __ldg(&csrc[j]),     e1 = __ldg(&csrc[j + 1]);
            int e2 = __ldg(&csrc[j + 2]), e3 = __ldg(&csrc[j + 3]);
            float a0 = __ldg(&ca[j]),     a1 = __ldg(&ca[j + 1]);
            float a2 = __ldg(&ca[j + 2]), a3 = __ldg(&ca[j + 3]);
            float d0, d1, d2, d3;
            if constexpr (D == 256) {
                uint4 k0 = *(const uint4*)&kh[e0 * D + c0];
                uint4 k1 = *(const uint4*)&kh[e1 * D + c0];
                uint4 k2 = *(const uint4*)&kh[e2 * D + c0];
                uint4 k3 = *(const uint4*)&kh[e3 * D + c0];
                uint4 v0 = *(const uint4*)&vh[e0 * D + c0];
                uint4 v1 = *(const uint4*)&vh[e1 * D + c0];
                uint4 v2 = *(const uint4*)&vh[e2 * D + c0];
                uint4 v3 = *(const uint4*)&vh[e3 * D + c0];
                d0 = dot_packed8(k0, qr); d1 = dot_packed8(k1, qr);
                d2 = dot_packed8(k2, qr); d3 = dot_packed8(k3, qr);
                #pragma unroll
                for (int off = 16; off > 0; off >>= 1) {
                    d0 += __shfl_xor_sync(0xffffffffu, d0, off);
                    d1 += __shfl_xor_sync(0xffffffffu, d1, off);
                    d2 += __shfl_xor_sync(0xffffffffu, d2, off);
                    d3 += __shfl_xor_sync(0xffffffffu, d3, off);
                }
                float p0 = __expf((d0 + a0 * qwe) * scale);
                float p1 = __expf((d1 + a1 * qwe) * scale);
                float p2 = __expf((d2 + a2 * qwe) * scale);
                float p3 = __expf((d3 + a3 * qwe) * scale);
                s += (p0 + p1) + (p2 + p3);
                pa = fmaf(p0, a0, pa); pa = fmaf(p1, a1, pa);
                pa = fmaf(p2, a2, pa); pa = fmaf(p3, a3, pa);
                acc_packed8(v0, p0, acc); acc_packed8(v1, p1, acc);
                acc_packed8(v2, p2, acc); acc_packed8(v3, p3, acc);
            } else {
                uint32_t k0 = *(const uint32_t*)&kh[e0 * D + c0];
                uint32_t k1 = *(const uint32_t*)&kh[e1 * D + c0];
                uint32_t k2 = *(const uint32_t*)&kh[e2 * D + c0];
                uint32_t k3 = *(const uint32_t*)&kh[e3 * D + c0];
                uint32_t v0 = *(const uint32_t*)&vh[e0 * D + c0];
                uint32_t v1 = *(const uint32_t*)&vh[e1 * D + c0];
                uint32_t v2 = *(const uint32_t*)&vh[e2 * D + c0];
                uint32_t v3 = *(const uint32_t*)&vh[e3 * D + c0];
                float2 f;
                f = __half22float2(*(__half2*)&k0); d0 = qr[0] * f.x + qr[1] * f.y;
                f = __half22float2(*(__half2*)&k1); d1 = qr[0] * f.x + qr[1] * f.y;
                f = __half22float2(*(__half2*)&k2); d2 = qr[0] * f.x + qr[1] * f.y;
                f = __half22float2(*(__half2*)&k3); d3 = qr[0] * f.x + qr[1] * f.y;
                #pragma unroll
                for (int off = 16; off > 0; off >>= 1) {
                    d0 += __shfl_xor_sync(0xffffffffu, d0, off);
                    d1 += __shfl_xor_sync(0xffffffffu, d1, off);
                    d2 += __shfl_xor_sync(0xffffffffu, d2, off);
                    d3 += __shfl_xor_sync(0xffffffffu, d3, off);
                }
                float p0 = __expf((d0 + a0 * qwe) * scale);
                float p1 = __expf((d1 + a1 * qwe) * scale);
                float p2 = __expf((d2 + a2 * qwe) * scale);
                float p3 = __expf((d3 + a3 * qwe) * scale);
                s += (p0 + p1) + (p2 + p3);
                pa = fmaf(p0, a0, pa); pa = fmaf(p1, a1, pa);
                pa = fmaf(p2, a2, pa); pa = fmaf(p3, a3, pa);
                f = __half22float2(*(__half2*)&v0); acc[0] = fmaf(p0, f.x, acc[0]); acc[1] = fmaf(p0, f.y, acc[1]);
                f = __half22float2(*(__half2*)&v1); acc[0] = fmaf(p1, f.x, acc[0]); acc[1] = fmaf(p1, f.y, acc[1]);
                f = __half22float2(*(__half2*)&v2); acc[0] = fmaf(p2, f.x, acc[0]); acc[1] = fmaf(p2, f.y, acc[1]);
                f = __half22float2(*(__half2*)&v3); acc[0] = fmaf(p3, f.x, acc[0]); acc[1] = fmaf(p3, f.y, acc[1]);
            }
        }
        for (; j < je; j++) {
            int e0 = __ldg(&csrc[j]);
            float a0 = __ldg(&ca[j]);
            float d0;
            if constexpr (D == 256) {
                uint4 k0 = *(const uint4*)&kh[e0 * D + c0];
                uint4 v0 = *(const uint4*)&vh[e0 * D + c0];
                d0 = dot_packed8(k0, qr);
                #pragma unroll
                for (int off = 16; off > 0; off >>= 1)
                    d0 += __shfl_xor_sync(0xffffffffu, d0, off);
                float p0 = __expf((d0 + a0 * qwe) * scale);
                s += p0;
                pa = fmaf(p0, a0, pa);
                acc_packed8(v0, p0, acc);
            } else {
                uint32_t k0 = *(const uint32_t*)&kh[e0 * D + c0];
                uint32_t v0 = *(const uint32_t*)&vh[e0 * D + c0];
                float2 f = __half22float2(*(__half2*)&k0);
                d0 = qr[0] * f.x + qr[1] * f.y;
                #pragma unroll
                for (int off = 16; off > 0; off >>= 1)
                    d0 += __shfl_xor_sync(0xffffffffu, d0, off);
                float p0 = __expf((d0 + a0 * qwe) * scale);
                s += p0;
                pa = fmaf(p0, a0, pa);
                f = __half22float2(*(__half2*)&v0);
                acc[0] = fmaf(p0, f.x, acc[0]); acc[1] = fmaf(p0, f.y, acc[1]);
            }
        }

        float inv = 1.f / (s + 1e-16f);
        float val[C];
        if constexpr (D == 256) {
            float4 s0 = *(const float4*)&o[n * D + c0];
            float4 s1 = *(const float4*)&o[n * D + c0 + 4];
            float sk[8] = {s0.x, s0.y, s0.z, s0.w, s1.x, s1.y, s1.z, s1.w};
            #pragma unroll
            for (int i = 0; i < 8; i++)
                val[i] = sk[i] + (acc[i] + pa * __ldg(&We[c0 + i])) * inv;
            *(float4*)&o[n * D + c0] = make_float4(val[0], val[1], val[2], val[3]);
            *(float4*)&o[n * D + c0 + 4] = make_float4(val[4], val[5], val[6], val[7]);
        } else {
            float2 s0 = *(const float2*)&o[n * D + c0];
            val[0] = s0.x + (acc[0] + pa * __ldg(&We[c0])) * inv;
            val[1] = s0.y + (acc[1] + pa * __ldg(&We[c0 + 1])) * inv;
            *(float2*)&o[n * D + c0] = make_float2(val[0], val[1]);
        }
        #pragma unroll
        for (int i = 0; i < C; i++) { su[i] += val[i]; sq[i] += val[i] * val[i]; }
    }

    #pragma unroll
    for (int i = 0; i < C; i++) {
        atomicAdd(&ssu[c0 + i], su[i]);
        atomicAdd(&ssq[c0 + i], sq[i]);
    }
    __syncthreads();
    for (int i = t; i < D; i += 256) {
        atomicAdd(&stats[i], ssu[i]);
        atomicAdd(&stats[D + i], ssq[i]);
    }
}

// ---------------- batch norm apply (finalize folded in) ----------------------
template <int D>
__global__ void bn_apply(const float* __restrict__ X, const float* __restrict__ stats,
                         const float* __restrict__ gamma, const float* __restrict__ beta,
                         float* __restrict__ xs, __half* __restrict__ hh,
                         float* __restrict__ pool, const int* __restrict__ batch,
                         int col_off) {
    constexpr int CG = D / 4;
    constexpr int RL = 256 / CG;
    constexpr int CHUNK = 16;
    int t = threadIdx.x;
    int cg = t % CG, rl = t / CG;
    int r0 = blockIdx.x * (RL * CHUNK) + rl * CHUNK;
    int c4 = cg * 4;
    const float invN = 1.f / (float)NN;
    float4 suv = *(const float4*)&stats[c4];
    float4 sqv = *(const float4*)&stats[D + c4];
    float4 mu, rs;
    mu.x = suv.x * invN; mu.y = suv.y * invN; mu.z = suv.z * invN; mu.w = suv.w * invN;
    rs.x = rsqrtf(sqv.x * invN - mu.x * mu.x + 1e-5f);
    rs.y = rsqrtf(sqv.y * invN - mu.y * mu.y + 1e-5f);
    rs.z = rsqrtf(sqv.z * invN - mu.z * mu.z + 1e-5f);
    rs.w = rsqrtf(sqv.w * invN - mu.w * mu.w + 1e-5f);
    float4 gm = *(const float4*)&gamma[c4];
    float4 bt = *(const float4*)&beta[c4];
    float4 acc = make_float4(0.f, 0.f, 0.f, 0.f);
    int curb = -1;
    for (int i = 0; i < CHUNK; i++) {
        int r = r0 + i;
        if (r >= NN) break;
        int b = __ldg(&batch[r]);
        if (b != curb) {
            if (curb >= 0) red_add_v4(&pool[curb * OUTW + col_off + c4], acc);
            acc = make_float4(0.f, 0.f, 0.f, 0.f);
            curb = b;
        }
        float4 xv = *(const float4*)&X[r * D + c4];
        float4 val;
        val.x = gm.x * (xv.x - mu.x) * rs.x + bt.x;
        val.y = gm.y * (xv.y - mu.y) * rs.y + bt.y;
        val.z = gm.z * (xv.z - mu.z) * rs.z + bt.z;
        val.w = gm.w * (xv.w - mu.w) * rs.w + bt.w;
        *(float4*)&xs[r * OUTW + col_off + c4] = val;
        if (hh) {
            __half2 h0 = __floats2half2_rn(val.x, val.y);
            __half2 h1 = __floats2half2_rn(val.z, val.w);
            *(uint2*)&hh[r * D + c4] = make_uint2(*(uint32_t*)&h0, *(uint32_t*)&h1);
        }
        acc.x += val.x; acc.y += val.y; acc.z += val.z; acc.w += val.w;
    }
    if (curb >= 0) red_add_v4(&pool[curb * OUTW + col_off + c4], acc);
}

__global__ void pool_div(float* pool, const float* __restrict__ cnt) {
    int i = blockIdx.x * blockDim.x + threadIdx.x;
    if (i >= GG * OUTW) return;
    pool[i] /= fmaxf(cnt[i / OUTW], 1.f);
}

// ---------------- launch -----------------------------------------------------
extern "C" void kernel_launch(void* const* d_in, const int* in_sizes, int n_in,
                              void* d_out, int out_size) {
    const float* x     = (const float*)d_in[0];
    const int*   ei    = (const int*)  d_in[1];
    const float* ea    = (const float*)d_in[2];
    const int*   batch = (const int*)  d_in[3];
    const float* Wq0 = (const float*)d_in[4];  const float* bq0 = (const float*)d_in[5];
    const float* Wk0 = (const float*)d_in[6];  const float* bk0 = (const float*)d_in[7];
    const float* Wv0 = (const float*)d_in[8];  const float* bv0 = (const float*)d_in[9];
    const float* We0 = (const float*)d_in[10];
    const float* Ws0 = (const float*)d_in[11]; const float* bs0 = (const float*)d_in[12];
    const float* gamma0 = (const float*)d_in[13]; const float* beta0 = (const float*)d_in[14];
    const float* Wq1 = (const float*)d_in[15]; const float* bq1 = (const float*)d_in[16];
    const float* Wk1 = (const float*)d_in[17]; const float* bk1 = (const float*)d_in[18];
    const float* Wv1 = (const float*)d_in[19]; const float* bv1 = (const float*)d_in[20];
    const float* We1 = (const float*)d_in[21];
    const float* Ws1 = (const float*)d_in[22]; const float* bs1 = (const float*)d_in[23];
    const float* gamma1 = (const float*)d_in[24]; const float* beta1 = (const float*)d_in[25];

    float* out  = (float*)d_out;
    float* pool = out;
    float* xs   = out + GG * OUTW;

    float *q, *o, *statsA, *statsB, *cnt, *bp0, *bp1, *ca;
    __half *kh, *vh, *xh, *hh, *Wph0, *Wph1;
    int *deg, *offs, *csrc;
    cudaGetSymbolAddress((void**)&q, g_q);
    cudaGetSymbolAddress((void**)&kh, g_kh);
    cudaGetSymbolAddress((void**)&vh, g_vh);
    cudaGetSymbolAddress((void**)&o, g_o);
    cudaGetSymbolAddress((void**)&xh, g_xh);
    cudaGetSymbolAddress((void**)&hh, g_hh);
    cudaGetSymbolAddress((void**)&deg, g_deg);
    cudaGetSymbolAddress((void**)&offs, g_offs);
    cudaGetSymbolAddress((void**)&csrc, g_csrc);
    cudaGetSymbolAddress((void**)&ca, g_ca);
    cudaGetSymbolAddress((void**)&statsA, g_statsA);
    cudaGetSymbolAddress((void**)&statsB, g_statsB);
    cudaGetSymbolAddress((void**)&cnt, g_cnt);
    cudaGetSymbolAddress((void**)&Wph0, g_Wph0);
    cudaGetSymbolAddress((void**)&bp0, g_bp0);
    cudaGetSymbolAddress((void**)&Wph1, g_Wph1);
    cudaGetSymbolAddress((void**)&bp1, g_bp1);

    const int TB = 256;

    // 0: prep   1: hist   2: scan   3: gemm L0 (profiled slot)   4: fill_csr
    prep<<<512, TB>>>(pool, cnt, deg, statsA, statsB, x, xh,
                      Wq0, Wk0, Wv0, Ws0, bq0, bk0, bv0, bs0,
                      Wq1, Wk1, Wv1, Ws1, bq1, bk1, bv1, bs1,
                      Wph0, bp0, Wph1, bp1);
    hist_count<<<(EE + TB - 1) / TB, TB>>>(ei, deg, batch, cnt);
    scan_kernel<<<1, 1024>>>(deg, offs);

    dim3 g0(4 * D0 / BN, (NN + BM - 1) / BM);
    hgemm4<<<g0, 256>>>(xh, Wph0, bp0, q, kh, vh, o, NN, FIN, FIN, D0);

    fill_csr<<<(EE + TB - 1) / TB, TB>>>(ei, ea, offs, deg, csrc, ca);

    node_agg<D0><<<1184, 256>>>(q, kh, vh, o, offs, deg, csrc, ca, We0, statsA, 1.f / 16.f);

    bn_apply<D0><<<(NN + 63) / 64, 256>>>(o, statsA, gamma0, beta0, xs, hh, pool, batch, 0);

    dim3 g1(4 * DIMV / BN, (NN + BM - 1) / BM);
    hgemm4<<<g1, 256>>>(hh, Wph1, bp1, q, kh, vh, o, NN, D0, D0, DIMV);

    node_agg<DIMV><<<1184, 256>>>(q, kh, vh, o, offs, deg, csrc, ca, We1, statsB, 1.f / 8.f);

    bn_apply<DIMV><<<(NN + 255) / 256, 256>>>(o, statsB, gamma1, beta1, xs, nullptr, pool,
                                              batch, D0);

    pool_div<<<(GG * OUTW + TB - 1) / TB, TB>>>(pool, cnt);
}

// round 11
// speedup vs baseline: 1.1155x; 1.0152x over previous
#include <cuda_runtime.h>
#include <cuda_fp16.h>
#include <cstdint>

#define NN   50000
#define EE   800000
#define FIN  128
#define D0   256
#define DIMV 64
#define GG   256
#define OUTW 320   // D0 + DIMV

// ---------------- scratch (device globals; no allocation) ----------------
__device__ float  g_q[NN * D0];
__device__ __half g_kh[NN * D0];
__device__ __half g_vh[NN * D0];
__device__ float  g_o[NN * D0];
__device__ __half g_xh[NN * FIN];
__device__ __half g_hh[NN * D0];
__device__ int    g_deg[NN];
__device__ int    g_offs[NN];
__device__ int    g_csrc[EE];
__device__ float  g_ca[EE];
__device__ float  g_statsA[2 * D0];
__device__ float  g_statsB[2 * DIMV];
__device__ float  g_cnt[GG];
__device__ __half g_Wph0[FIN * 4 * D0];
__device__ float  g_bp0[4 * D0];
__device__ __half g_Wph1[D0 * 4 * DIMV];
__device__ float  g_bp1[4 * DIMV];

// ---------------- helpers ----------------
__device__ __forceinline__ void red_add_v4(float* ptr, float4 v) {
    asm volatile("red.global.add.v4.f32 [%0], {%1,%2,%3,%4};"
                 :: "l"(ptr), "f"(v.x), "f"(v.y), "f"(v.z), "f"(v.w) : "memory");
}
__device__ __forceinline__ uint32_t smem_u32(const void* p) {
    return (uint32_t)__cvta_generic_to_shared(p);
}
__device__ __forceinline__ void cp_async16(uint32_t dst, const void* src, int src_sz) {
    asm volatile("cp.async.cg.shared.global [%0], [%1], 16, %2;"
                 :: "r"(dst), "l"(src), "r"(src_sz));
}
__device__ __forceinline__ void cp_commit() {
    asm volatile("cp.async.commit_group;");
}
__device__ __forceinline__ void ldsm_x4(uint32_t& r0, uint32_t& r1, uint32_t& r2,
                                        uint32_t& r3, uint32_t addr) {
    asm volatile("ldmatrix.sync.aligned.m8n8.x4.shared.b16 {%0,%1,%2,%3}, [%4];"
                 : "=r"(r0), "=r"(r1), "=r"(r2), "=r"(r3) : "r"(addr));
}
__device__ __forceinline__ void ldsm_x4_t(uint32_t& r0, uint32_t& r1, uint32_t& r2,
                                          uint32_t& r3, uint32_t addr) {
    asm volatile("ldmatrix.sync.aligned.m8n8.x4.trans.shared.b16 {%0,%1,%2,%3}, [%4];"
                 : "=r"(r0), "=r"(r1), "=r"(r2), "=r"(r3) : "r"(addr));
}
__device__ __forceinline__ void mma_f16(float& c0, float& c1, float& c2, float& c3,
                                        uint32_t a0, uint32_t a1, uint32_t a2, uint32_t a3,
                                        uint32_t b0, uint32_t b1) {
    asm volatile("mma.sync.aligned.m16n8k16.row.col.f32.f16.f16.f32 "
                 "{%0,%1,%2,%3}, {%4,%5,%6,%7}, {%8,%9}, {%0,%1,%2,%3};"
                 : "+f"(c0), "+f"(c1), "+f"(c2), "+f"(c3)
                 : "r"(a0), "r"(a1), "r"(a2), "r"(a3), "r"(b0), "r"(b1));
}

// ---------------- prep: zeroing + fp16 weight packing + x conversion ---------
__global__ void prep(float* pool, float* cnt, int* deg, float* statsA, float* statsB,
                     const float* __restrict__ x, __half* xh,
                     const float* __restrict__ Wq0, const float* __restrict__ Wk0,
                     const float* __restrict__ Wv0, const float* __restrict__ Ws0,
                     const float* __restrict__ bq0, const float* __restrict__ bk0,
                     const float* __restrict__ bv0, const float* __restrict__ bs0,
                     const float* __restrict__ Wq1, const float* __restrict__ Wk1,
                     const float* __restrict__ Wv1, const float* __restrict__ Ws1,
                     const float* __restrict__ bq1, const float* __restrict__ bk1,
                     const float* __restrict__ bv1, const float* __restrict__ bs1,
                     __half* Wph0, float* bp0, __half* Wph1, float* bp1) {
    int gs = gridDim.x * blockDim.x;
    int i0 = blockIdx.x * blockDim.x + threadIdx.x;
    for (int i = i0; i < GG * OUTW; i += gs) pool[i] = 0.f;
    for (int i = i0; i < GG; i += gs) cnt[i] = 0.f;
    for (int i = i0; i < NN; i += gs) deg[i] = 0;
    for (int i = i0; i < 2 * D0; i += gs) statsA[i] = 0.f;
    for (int i = i0; i < 2 * DIMV; i += gs) statsB[i] = 0.f;
    for (int i = i0; i < NN * FIN / 2; i += gs) {
        float2 v = *(const float2*)&x[i * 2];
        *(__half2*)&xh[i * 2] = __floats2half2_rn(v.x, v.y);
    }
    for (int i = i0; i < FIN * 4 * D0; i += gs) {
        int kk = i / (4 * D0), c = i % (4 * D0);
        int sel = c / D0, cc = c % D0;
        const float* W = sel == 0 ? Wq0 : sel == 1 ? Wk0 : sel == 2 ? Wv0 : Ws0;
        Wph0[i] = __float2half_rn(W[kk * D0 + cc]);
    }
    for (int i = i0; i < 4 * D0; i += gs) {
        int sel = i / D0, cc = i % D0;
        const float* b = sel == 0 ? bq0 : sel == 1 ? bk0 : sel == 2 ? bv0 : bs0;
        bp0[i] = b[cc];
    }
    for (int i = i0; i < D0 * 4 * DIMV; i += gs) {
        int kk = i / (4 * DIMV), c = i % (4 * DIMV);
        int sel = c / DIMV, cc = c % DIMV;
        const float* W = sel == 0 ? Wq1 : sel == 1 ? Wk1 : sel == 2 ? Wv1 : Ws1;
        Wph1[i] = __float2half_rn(W[kk * DIMV + cc]);
    }
    for (int i = i0; i < 4 * DIMV; i += gs) {
        int sel = i / DIMV, cc = i % DIMV;
        const float* b = sel == 0 ? bq1 : sel == 1 ? bk1 : sel == 2 ? bv1 : bs1;
        bp1[i] = b[cc];
    }
}

// ---------------- CSR build --------------------------------------------------
__global__ void hist_count(const int* __restrict__ ei, int* deg,
                           const int* __restrict__ batch, float* cnt) {
    int i = blockIdx.x * blockDim.x + threadIdx.x;
    if (i < EE) atomicAdd(&deg[ei[EE + i]], 1);
    if (i < NN) atomicAdd(&cnt[batch[i]], 1.f);
}

__global__ void scan_kernel(int* deg, int* offs) {   // 1 block, 1024 threads
    __shared__ int ps[1024];
    int t = threadIdx.x;
    const int CH = (NN + 1023) / 1024;
    int base = t * CH;
    int sum = 0;
    for (int i = 0; i < CH; i++) {
        int idx = base + i;
        if (idx < NN) sum += deg[idx];
    }
    ps[t] = sum;
    __syncthreads();
    for (int off = 1; off < 1024; off <<= 1) {
        int v = (t >= off) ? ps[t - off] : 0;
        __syncthreads();
        ps[t] += v;
        __syncthreads();
    }
    int run = (t > 0) ? ps[t - 1] : 0;
    for (int i = 0; i < CH; i++) {
        int idx = base + i;
        if (idx < NN) {
            offs[idx] = run;
            run += deg[idx];
            deg[idx] = 0;
        }
    }
}

__global__ void fill_csr(const int* __restrict__ ei, const float* __restrict__ ea,
                         const int* __restrict__ offs, int* deg,
                         int* csrc, float* ca) {
    int e = blockIdx.x * blockDim.x + threadIdx.x;
    if (e >= EE) return;
    int dst = ei[EE + e];
    int slot = offs[dst] + atomicAdd(&deg[dst], 1);
    csrc[slot] = ei[e];
    ca[slot] = ea[e];
}

// ---------------- fp16 tensor-core GEMM, cp.async double-buffered ------------
#define BM 128
#define BN 128
#define BKH 32
#define APITCH 40
#define BPITCH 136

__global__ __launch_bounds__(256)
void hgemm4(const __half* __restrict__ A, const __half* __restrict__ Wp,
            const float* __restrict__ bp,
            float* __restrict__ Oq, __half* __restrict__ Ok,
            __half* __restrict__ Ov, float* __restrict__ Oo,
            int M, int K, int lda, int D) {
    const int Nc = 4 * D;
    __shared__ __half As[2][BM][APITCH];
    __shared__ __half Bs[2][BKH][BPITCH];

    int t = threadIdx.x;
    int lane = t & 31;
    int warp = t >> 5;
    int wm = warp >> 2;
    int wn = warp & 3;
    int g = lane >> 2;
    int t4 = lane & 3;
    int row0 = blockIdx.y * BM;
    int col0 = blockIdx.x * BN;

    float acc[4][4][4] = {};

    int a_r0 = t >> 2, a_c0 = (t & 3) * 8;
    int a_r1 = (t + 256) >> 2, a_c1 = ((t + 256) & 3) * 8;
    int b_r0 = t >> 4, b_c0 = (t & 15) * 8;
    int b_r1 = (t + 256) >> 4, b_c1 = ((t + 256) & 15) * 8;

    int a_row_l = lane & 15;
    int a_koff = (lane >> 4) * 8;
    int b_krow_l = ((lane >> 3) & 1) * 8 + (lane & 7);
    int b_noff = (lane >> 4) * 8;

    const int KT = K / BKH;

    auto load_tiles = [&](int st, int k0) {
        int gr0 = row0 + a_r0, gr1 = row0 + a_r1;
        cp_async16(smem_u32(&As[st][a_r0][a_c0]), &A[gr0 * lda + k0 + a_c0],
                   gr0 < M ? 16 : 0);
        cp_async16(smem_u32(&As[st][a_r1][a_c1]), &A[gr1 * lda + k0 + a_c1],
                   gr1 < M ? 16 : 0);
        cp_async16(smem_u32(&Bs[st][b_r0][b_c0]), &Wp[(k0 + b_r0) * Nc + col0 + b_c0], 16);
        cp_async16(smem_u32(&Bs[st][b_r1][b_c1]), &Wp[(k0 + b_r1) * Nc + col0 + b_c1], 16);
    };

    load_tiles(0, 0);
    cp_commit();

    for (int kt = 0; kt < KT; kt++) {
        int st = kt & 1;
        if (kt + 1 < KT) {
            load_tiles(st ^ 1, (kt + 1) * BKH);
            cp_commit();
            asm volatile("cp.async.wait_group 1;");
        } else {
            asm volatile("cp.async.wait_group 0;");
        }
        __syncthreads();

        #pragma unroll
        for (int ks = 0; ks < 2; ks++) {
            int kk = ks * 16;
            uint32_t af[4][4], bf[4][2];
            #pragma unroll
            for (int mt = 0; mt < 4; mt++) {
                int rb = wm * 64 + mt * 16;
                uint32_t addr = smem_u32(&As[st][rb + a_row_l][kk + a_koff]);
                ldsm_x4(af[mt][0], af[mt][1], af[mt][2], af[mt][3], addr);
            }
            #pragma unroll
            for (int p = 0; p < 2; p++) {
                int n0 = wn * 32 + p * 16;
                uint32_t addr = smem_u32(&Bs[st][kk + b_krow_l][n0 + b_noff]);
                ldsm_x4_t(bf[2 * p][0], bf[2 * p][1], bf[2 * p + 1][0], bf[2 * p + 1][1],
                          addr);
            }
            #pragma unroll
            for (int mt = 0; mt < 4; mt++)
                #pragma unroll
                for (int nt = 0; nt < 4; nt++)
                    mma_f16(acc[mt][nt][0], acc[mt][nt][1], acc[mt][nt][2], acc[mt][nt][3],
                            af[mt][0], af[mt][1], af[mt][2], af[mt][3],
                            bf[nt][0], bf[nt][1]);
        }
        __syncthreads();
    }

    #pragma unroll
    for (int nt = 0; nt < 4; nt++) {
        int cg = col0 + wn * 32 + nt * 8;
        int sel = cg / D;
        int cc = cg % D;
        int c0 = cc + 2 * t4;
        float2 bias = *(const float2*)&bp[cg + 2 * t4];
        if (sel == 1 || sel == 2) {
            __half* O = (sel == 1) ? Ok : Ov;
            #pragma unroll
            for (int mt = 0; mt < 4; mt++) {
                int r0 = row0 + wm * 64 + mt * 16 + g;
                if (r0 < M)
                    *(__half2*)&O[r0 * D + c0] =
                        __floats2half2_rn(acc[mt][nt][0] + bias.x, acc[mt][nt][1] + bias.y);
                if (r0 + 8 < M)
                    *(__half2*)&O[(r0 + 8) * D + c0] =
                        __floats2half2_rn(acc[mt][nt][2] + bias.x, acc[mt][nt][3] + bias.y);
            }
        } else {
            float* O = (sel == 0) ? Oq : Oo;
            #pragma unroll
            for (int mt = 0; mt < 4; mt++) {
                int r0 = row0 + wm * 64 + mt * 16 + g;
                if (r0 < M)
                    *(float2*)&O[r0 * D + c0] =
                        make_float2(acc[mt][nt][0] + bias.x, acc[mt][nt][1] + bias.y);
                if (r0 + 8 < M)
                    *(float2*)&O[(r0 + 8) * D + c0] =
                        make_float2(acc[mt][nt][2] + bias.x, acc[mt][nt][3] + bias.y);
            }
        }
    }
}

// ---------------- packed-dot helpers -----------------------------------------
__device__ __forceinline__ float dot_packed8(uint4 u, const float* qr) {
    float d = 0.f;
    float2 f;
    f = __half22float2(*(__half2*)&u.x); d = fmaf(qr[0], f.x, d); d = fmaf(qr[1], f.y, d);
    f = __half22float2(*(__half2*)&u.y); d = fmaf(qr[2], f.x, d); d = fmaf(qr[3], f.y, d);
    f = __half22float2(*(__half2*)&u.z); d = fmaf(qr[4], f.x, d); d = fmaf(qr[5], f.y, d);
    f = __half22float2(*(__half2*)&u.w); d = fmaf(qr[6], f.x, d); d = fmaf(qr[7], f.y, d);
    return d;
}
__device__ __forceinline__ void acc_packed8(uint4 u, float p, float* acc) {
    float2 f;
    f = __half22float2(*(__half2*)&u.x); acc[0] = fmaf(p, f.x, acc[0]); acc[1] = fmaf(p, f.y, acc[1]);
    f = __half22float2(*(__half2*)&u.y); acc[2] = fmaf(p, f.x, acc[2]); acc[3] = fmaf(p, f.y, acc[3]);
    f = __half22float2(*(__half2*)&u.z); acc[4] = fmaf(p, f.x, acc[4]); acc[5] = fmaf(p, f.y, acc[5]);
    f = __half22float2(*(__half2*)&u.w); acc[6] = fmaf(p, f.x, acc[6]); acc[7] = fmaf(p, f.y, acc[7]);
}

// ---------------- node aggregation D=256: cp.async smem-pipelined ------------
// 128-thread blocks (4 warps). Warp per node. Per 4-edge batch each lane
// cp.asyncs its own 16B of 4 k-rows + 4 v-rows into a per-warp double buffer
// while computing the previous batch from smem. Each lane reads only bytes it
// copied itself -> no syncwarp, pure per-thread pipeline.
__global__ __launch_bounds__(128)
void node_agg256(const float* __restrict__ q, const __half* __restrict__ kh,
                 const __half* __restrict__ vh, float* __restrict__ o,
                 const int* __restrict__ offs, const int* __restrict__ deg,
                 const int* __restrict__ csrc, const float* __restrict__ ca,
                 const float* __restrict__ We, float* __restrict__ stats, float scale) {
    constexpr int D = 256;
    constexpr int C = 8;
    __shared__ __align__(16) __half kv[4][2][8][256];  // [warp][stage][row][512B]
    __shared__ float ssu[D], ssq[D];
    int t = threadIdx.x, lane = t & 31, w = t >> 5;
    for (int i = t; i < D; i += 128) { ssu[i] = 0.f; ssq[i] = 0.f; }
    __syncthreads();
    int c0 = lane * C;
    float su[C] = {}, sq[C] = {};
    int wg = blockIdx.x * 4 + w, tw = gridDim.x * 4;

    uint32_t sb0 = smem_u32(&kv[w][0][0][lane * 8]);
    uint32_t sb1 = smem_u32(&kv[w][1][0][lane * 8]);

    for (int n = wg; n < NN; n += tw) {
        float qr[C];
        {
            float4 a0 = *(const float4*)&q[n * D + c0];
            float4 a1 = *(const float4*)&q[n * D + c0 + 4];
            qr[0] = a0.x; qr[1] = a0.y; qr[2] = a0.z; qr[3] = a0.w;
            qr[4] = a1.x; qr[5] = a1.y; qr[6] = a1.z; qr[7] = a1.w;
        }
        float qwe = 0.f;
        #pragma unroll
        for (int i = 0; i < C; i++) qwe += qr[i] * __ldg(&We[c0 + i]);
        #pragma unroll
        for (int off = 16; off > 0; off >>= 1)
            qwe += __shfl_xor_sync(0xffffffffu, qwe, off);

        float acc[C] = {};
        float s = 0.f, pa = 0.f;
        int jb = offs[n], dg = deg[n];
        int nb = dg >> 2;

        auto prefetch = [&](int jj, uint32_t sb) {
            int e0 = __ldg(&csrc[jj]),     e1 = __ldg(&csrc[jj + 1]);
            int e2 = __ldg(&csrc[jj + 2]), e3 = __ldg(&csrc[jj + 3]);
            cp_async16(sb + 0 * 512, &kh[e0 * D + c0], 16);
            cp_async16(sb + 1 * 512, &kh[e1 * D + c0], 16);
            cp_async16(sb + 2 * 512, &kh[e2 * D + c0], 16);
            cp_async16(sb + 3 * 512, &kh[e3 * D + c0], 16);
            cp_async16(sb + 4 * 512, &vh[e0 * D + c0], 16);
            cp_async16(sb + 5 * 512, &vh[e1 * D + c0], 16);
            cp_async16(sb + 6 * 512, &vh[e2 * D + c0], 16);
            cp_async16(sb + 7 * 512, &vh[e3 * D + c0], 16);
        };

        if (nb > 0) { prefetch(jb, sb0); cp_commit(); }
        int j = jb;
        int stage = 0;
        for (int b = 0; b < nb; b++) {
            if (b + 1 < nb) {
                prefetch(j + 4, stage ? sb0 : sb1);
                cp_commit();
                asm volatile("cp.async.wait_group 1;");
            } else {
                asm volatile("cp.async.wait_group 0;");
            }
            const __half* buf = &kv[w][stage][0][lane * 8];
            float a0 = __ldg(&ca[j]),     a1 = __ldg(&ca[j + 1]);
            float a2 = __ldg(&ca[j + 2]), a3 = __ldg(&ca[j + 3]);
            uint4 k0 = *(const uint4*)(buf + 0 * 256);
            uint4 k1 = *(const uint4*)(buf + 1 * 256);
            uint4 k2 = *(const uint4*)(buf + 2 * 256);
            uint4 k3 = *(const uint4*)(buf + 3 * 256);
            float d0 = dot_packed8(k0, qr), d1 = dot_packed8(k1, qr);
            float d2 = dot_packed8(k2, qr), d3 = dot_packed8(k3, qr);
            #pragma unroll
            for (int off = 16; off > 0; off >>= 1) {
                d0 += __shfl_xor_sync(0xffffffffu, d0, off);
                d1 += __shfl_xor_sync(0xffffffffu, d1, off);
                d2 += __shfl_xor_sync(0xffffffffu, d2, off);
                d3 += __shfl_xor_sync(0xffffffffu, d3, off);
            }
            float p0 = __expf((d0 + a0 * qwe) * scale);
            float p1 = __expf((d1 + a1 * qwe) * scale);
            float p2 = __expf((d2 + a2 * qwe) * scale);
            float p3 = __expf((d3 + a3 * qwe) * scale);
            s += (p0 + p1) + (p2 + p3);
            pa = fmaf(p0, a0, pa); pa = fmaf(p1, a1, pa);
            pa = fmaf(p2, a2, pa); pa = fmaf(p3, a3, pa);
            uint4 v0 = *(const uint4*)(buf + 4 * 256);
            uint4 v1 = *(const uint4*)(buf + 5 * 256);
            uint4 v2 = *(const uint4*)(buf + 6 * 256);
            uint4 v3 = *(const uint4*)(buf + 7 * 256);
            acc_packed8(v0, p0, acc); acc_packed8(v1, p1, acc);
            acc_packed8(v2, p2, acc); acc_packed8(v3, p3, acc);
            j += 4;
            stage ^= 1;
        }
        // tail edges (direct LDG)
        int je = jb + dg;
        for (; j < je; j++) {
            int e0 = __ldg(&csrc[j]);
            float a0 = __ldg(&ca[j]);
            uint4 k0 = *(const uint4*)&kh[e0 * D + c0];
            uint4 v0 = *(const uint4*)&vh[e0 * D + c0];
            float d0 = dot_packed8(k0, qr);
            #pragma unroll
            for (int off = 16; off > 0; off >>= 1)
                d0 += __shfl_xor_sync(0xffffffffu, d0, off);
            float p0 = __expf((d0 + a0 * qwe) * scale);
            s += p0;
            pa = fmaf(p0, a0, pa);
            acc_packed8(v0, p0, acc);
        }

        float inv = 1.f / (s + 1e-16f);
        float val[C];
        float4 s0 = *(const float4*)&o[n * D + c0];
        float4 s1 = *(const float4*)&o[n * D + c0 + 4];
        float sk[8] = {s0.x, s0.y, s0.z, s0.w, s1.x, s1.y, s1.z, s1.w};
        #pragma unroll
        for (int i = 0; i < 8; i++)
            val[i] = sk[i] + (acc[i] + pa * __ldg(&We[c0 + i])) * inv;
        *(float4*)&o[n * D + c0] = make_float4(val[0], val[1], val[2], val[3]);
        *(float4*)&o[n * D + c0 + 4] = make_float4(val[4], val[5], val[6], val[7]);
        #pragma unroll
        for (int i = 0; i < C; i++) { su[i] += val[i]; sq[i] += val[i] * val[i]; }
    }

    #pragma unroll
    for (int i = 0; i < C; i++) {
        atomicAdd(&ssu[c0 + i], su[i]);
        atomicAdd(&ssq[c0 + i], sq[i]);
    }
    __syncthreads();
    for (int i = t; i < D; i += 128) {
        atomicAdd(&stats[i], ssu[i]);
        atomicAdd(&stats[D + i], ssq[i]);
    }
}

// ---------------- node aggregation D=64: R10 direct path ---------------------
__global__ __launch_bounds__(256, 3)
void node_agg64(const float* __restrict__ q, const __half* __restrict__ kh,
                const __half* __restrict__ vh, float* __restrict__ o,
                const int* __restrict__ offs, const int* __restrict__ deg,
                const int* __restrict__ csrc, const float* __restrict__ ca,
                const float* __restrict__ We, float* __restrict__ stats, float scale) {
    constexpr int D = 64;
    constexpr int C = 2;
    __shared__ float ssu[D], ssq[D];
    int t = threadIdx.x, lane = t & 31, w = t >> 5;
    for (int i = t; i < D; i += 256) { ssu[i] = 0.f; ssq[i] = 0.f; }
    __syncthreads();
    int c0 = lane * C;
    float su[C] = {}, sq[C] = {};
    int wg = blockIdx.x * 8 + w, tw = gridDim.x * 8;

    for (int n = wg; n < NN; n += tw) {
        float qr[C];
        float2 a0v = *(const float2*)&q[n * D + c0];
        qr[0] = a0v.x; qr[1] = a0v.y;
        float qwe = qr[0] * __ldg(&We[c0]) + qr[1] * __ldg(&We[c0 + 1]);
        #pragma unroll
        for (int off = 16; off > 0; off >>= 1)
            qwe += __shfl_xor_sync(0xffffffffu, qwe, off);

        float acc[C] = {};
        float s = 0.f, pa = 0.f;
        int jb = offs[n], je = jb + deg[n];
        int j = jb;
        for (; j + 4 <= je; j += 4) {
            int e0 = __ldg(&csrc[j]),     e1 = __ldg(&csrc[j + 1]);
            int e2 = __ldg(&csrc[j + 2]), e3 = __ldg(&csrc[j + 3]);
            float a0 = __ldg(&ca[j]),     a1 = __ldg(&ca[j + 1]);
            float a2 = __ldg(&ca[j + 2]), a3 = __ldg(&ca[j + 3]);
            uint32_t k0 = *(const uint32_t*)&kh[e0 * D + c0];
            uint32_t k1 = *(const uint32_t*)&kh[e1 * D + c0];
            uint32_t k2 = *(const uint32_t*)&kh[e2 * D + c0];
            uint32_t k3 = *(const uint32_t*)&kh[e3 * D + c0];
            uint32_t v0 = *(const uint32_t*)&vh[e0 * D + c0];
            uint32_t v1 = *(const uint32_t*)&vh[e1 * D + c0];
            uint32_t v2 = *(const uint32_t*)&vh[e2 * D + c0];
            uint32_t v3 = *(const uint32_t*)&vh[e3 * D + c0];
            float d0, d1, d2, d3;
            float2 f;
            f = __half22float2(*(__half2*)&k0); d0 = qr[0] * f.x + qr[1] * f.y;
            f = __half22float2(*(__half2*)&k1); d1 = qr[0] * f.x + qr[1] * f.y;
            f = __half22float2(*(__half2*)&k2); d2 = qr[0] * f.x + qr[1] * f.y;
            f = __half22float2(*(__half2*)&k3); d3 = qr[0] * f.x + qr[1] * f.y;
            #pragma unroll
            for (int off = 16; off > 0; off >>= 1) {
                d0 += __shfl_xor_sync(0xffffffffu, d0, off);
                d1 += __shfl_xor_sync(0xffffffffu, d1, off);
                d2 += __shfl_xor_sync(0xffffffffu, d2, off);
                d3 += __shfl_xor_sync(0xffffffffu, d3, off);
            }
            float p0 = __expf((d0 + a0 * qwe) * scale);
            float p1 = __expf((d1 + a1 * qwe) * scale);
            float p2 = __expf((d2 + a2 * qwe) * scale);
            float p3 = __expf((d3 + a3 * qwe) * scale);
            s += (p0 + p1) + (p2 + p3);
            pa = fmaf(p0, a0, pa); pa = fmaf(p1, a1, pa);
            pa = fmaf(p2, a2, pa); pa = fmaf(p3, a3, pa);
            f = __half22float2(*(__half2*)&v0); acc[0] = fmaf(p0, f.x, acc[0]); acc[1] = fmaf(p0, f.y, acc[1]);
            f = __half22float2(*(__half2*)&v1); acc[0] = fmaf(p1, f.x, acc[0]); acc[1] = fmaf(p1, f.y, acc[1]);
            f = __half22float2(*(__half2*)&v2); acc[0] = fmaf(p2, f.x, acc[0]); acc[1] = fmaf(p2, f.y, acc[1]);
            f = __half22float2(*(__half2*)&v3); acc[0] = fmaf(p3, f.x, acc[0]); acc[1] = fmaf(p3, f.y, acc[1]);
        }
        for (; j < je; j++) {
            int e0 = __ldg(&csrc[j]);
            float a0 = __ldg(&ca[j]);
            uint32_t k0 = *(const uint32_t*)&kh[e0 * D + c0];
            uint32_t v0 = *(const uint32_t*)&vh[e0 * D + c0];
            float2 f = __half22float2(*(__half2*)&k0);
            float d0 = qr[0] * f.x + qr[1] * f.y;
            #pragma unroll
            for (int off = 16; off > 0; off >>= 1)
                d0 += __shfl_xor_sync(0xffffffffu, d0, off);
            float p0 = __expf((d0 + a0 * qwe) * scale);
            s += p0;
            pa = fmaf(p0, a0, pa);
            f = __half22float2(*(__half2*)&v0);
            acc[0] = fmaf(p0, f.x, acc[0]); acc[1] = fmaf(p0, f.y, acc[1]);
        }

        float inv = 1.f / (s + 1e-16f);
        float val[C];
        float2 s0 = *(const float2*)&o[n * D + c0];
        val[0] = s0.x + (acc[0] + pa * __ldg(&We[c0])) * inv;
        val[1] = s0.y + (acc[1] + pa * __ldg(&We[c0 + 1])) * inv;
        *(float2*)&o[n * D + c0] = make_float2(val[0], val[1]);
        #pragma unroll
        for (int i = 0; i < C; i++) { su[i] += val[i]; sq[i] += val[i] * val[i]; }
    }

    #pragma unroll
    for (int i = 0; i < C; i++) {
        atomicAdd(&ssu[c0 + i], su[i]);
        atomicAdd(&ssq[c0 + i], sq[i]);
    }
    __syncthreads();
    for (int i = t; i < D; i += 256) {
        atomicAdd(&stats[i], ssu[i]);
        atomicAdd(&stats[D + i], ssq[i]);
    }
}

// ---------------- batch norm apply (finalize folded in) ----------------------
template <int D>
__global__ void bn_apply(const float* __restrict__ X, const float* __restrict__ stats,
                         const float* __restrict__ gamma, const float* __restrict__ beta,
                         float* __restrict__ xs, __half* __restrict__ hh,
                         float* __restrict__ pool, const int* __restrict__ batch,
                         int col_off) {
    constexpr int CG = D / 4;
    constexpr int RL = 256 / CG;
    constexpr int CHUNK = 16;
    int t = threadIdx.x;
    int cg = t % CG, rl = t / CG;
    int r0 = blockIdx.x * (RL * CHUNK) + rl * CHUNK;
    int c4 = cg * 4;
    const float invN = 1.f / (float)NN;
    float4 suv = *(const float4*)&stats[c4];
    float4 sqv = *(const float4*)&stats[D + c4];
    float4 mu, rs;
    mu.x = suv.x * invN; mu.y = suv.y * invN; mu.z = suv.z * invN; mu.w = suv.w * invN;
    rs.x = rsqrtf(sqv.x * invN - mu.x * mu.x + 1e-5f);
    rs.y = rsqrtf(sqv.y * invN - mu.y * mu.y + 1e-5f);
    rs.z = rsqrtf(sqv.z * invN - mu.z * mu.z + 1e-5f);
    rs.w = rsqrtf(sqv.w * invN - mu.w * mu.w + 1e-5f);
    float4 gm = *(const float4*)&gamma[c4];
    float4 bt = *(const float4*)&beta[c4];
    float4 acc = make_float4(0.f, 0.f, 0.f, 0.f);
    int curb = -1;
    for (int i = 0; i < CHUNK; i++) {
        int r = r0 + i;
        if (r >= NN) break;
        int b = __ldg(&batch[r]);
        if (b != curb) {
            if (curb >= 0) red_add_v4(&pool[curb * OUTW + col_off + c4], acc);
            acc = make_float4(0.f, 0.f, 0.f, 0.f);
            curb = b;
        }
        float4 xv = *(const float4*)&X[r * D + c4];
        float4 val;
        val.x = gm.x * (xv.x - mu.x) * rs.x + bt.x;
        val.y = gm.y * (xv.y - mu.y) * rs.y + bt.y;
        val.z = gm.z * (xv.z - mu.z) * rs.z + bt.z;
        val.w = gm.w * (xv.w - mu.w) * rs.w + bt.w;
        *(float4*)&xs[r * OUTW + col_off + c4] = val;
        if (hh) {
            __half2 h0 = __floats2half2_rn(val.x, val.y);
            __half2 h1 = __floats2half2_rn(val.z, val.w);
            *(uint2*)&hh[r * D + c4] = make_uint2(*(uint32_t*)&h0, *(uint32_t*)&h1);
        }
        acc.x += val.x; acc.y += val.y; acc.z += val.z; acc.w += val.w;
    }
    if (curb >= 0) red_add_v4(&pool[curb * OUTW + col_off + c4], acc);
}

__global__ void pool_div(float* pool, const float* __restrict__ cnt) {
    int i = blockIdx.x * blockDim.x + threadIdx.x;
    if (i >= GG * OUTW) return;
    pool[i] /= fmaxf(cnt[i / OUTW], 1.f);
}

// ---------------- launch -----------------------------------------------------
extern "C" void kernel_launch(void* const* d_in, const int* in_sizes, int n_in,
                              void* d_out, int out_size) {
    const float* x     = (const float*)d_in[0];
    const int*   ei    = (const int*)  d_in[1];
    const float* ea    = (const float*)d_in[2];
    const int*   batch = (const int*)  d_in[3];
    const float* Wq0 = (const float*)d_in[4];  const float* bq0 = (const float*)d_in[5];
    const float* Wk0 = (const float*)d_in[6];  const float* bk0 = (const float*)d_in[7];
    const float* Wv0 = (const float*)d_in[8];  const float* bv0 = (const float*)d_in[9];
    const float* We0 = (const float*)d_in[10];
    const float* Ws0 = (const float*)d_in[11]; const float* bs0 = (const float*)d_in[12];
    const float* gamma0 = (const float*)d_in[13]; const float* beta0 = (const float*)d_in[14];
    const float* Wq1 = (const float*)d_in[15]; const float* bq1 = (const float*)d_in[16];
    const float* Wk1 = (const float*)d_in[17]; const float* bk1 = (const float*)d_in[18];
    const float* Wv1 = (const float*)d_in[19]; const float* bv1 = (const float*)d_in[20];
    const float* We1 = (const float*)d_in[21];
    const float* Ws1 = (const float*)d_in[22]; const float* bs1 = (const float*)d_in[23];
    const float* gamma1 = (const float*)d_in[24]; const float* beta1 = (const float*)d_in[25];

    float* out  = (float*)d_out;
    float* pool = out;
    float* xs   = out + GG * OUTW;

    float *q, *o, *statsA, *statsB, *cnt, *bp0, *bp1, *ca;
    __half *kh, *vh, *xh, *hh, *Wph0, *Wph1;
    int *deg, *offs, *csrc;
    cudaGetSymbolAddress((void**)&q, g_q);
    cudaGetSymbolAddress((void**)&kh, g_kh);
    cudaGetSymbolAddress((void**)&vh, g_vh);
    cudaGetSymbolAddress((void**)&o, g_o);
    cudaGetSymbolAddress((void**)&xh, g_xh);
    cudaGetSymbolAddress((void**)&hh, g_hh);
    cudaGetSymbolAddress((void**)&deg, g_deg);
    cudaGetSymbolAddress((void**)&offs, g_offs);
    cudaGetSymbolAddress((void**)&csrc, g_csrc);
    cudaGetSymbolAddress((void**)&ca, g_ca);
    cudaGetSymbolAddress((void**)&statsA, g_statsA);
    cudaGetSymbolAddress((void**)&statsB, g_statsB);
    cudaGetSymbolAddress((void**)&cnt, g_cnt);
    cudaGetSymbolAddress((void**)&Wph0, g_Wph0);
    cudaGetSymbolAddress((void**)&bp0, g_bp0);
    cudaGetSymbolAddress((void**)&Wph1, g_Wph1);
    cudaGetSymbolAddress((void**)&bp1, g_bp1);

    const int TB = 256;

    // 0: prep   1: hist   2: scan   3: gemm L0 (profiled slot)   4: fill_csr
    prep<<<512, TB>>>(pool, cnt, deg, statsA, statsB, x, xh,
                      Wq0, Wk0, Wv0, Ws0, bq0, bk0, bv0, bs0,
                      Wq1, Wk1, Wv1, Ws1, bq1, bk1, bv1, bs1,
                      Wph0, bp0, Wph1, bp1);
    hist_count<<<(EE + TB - 1) / TB, TB>>>(ei, deg, batch, cnt);
    scan_kernel<<<1, 1024>>>(deg, offs);

    dim3 g0(4 * D0 / BN, (NN + BM - 1) / BM);
    hgemm4<<<g0, 256>>>(xh, Wph0, bp0, q, kh, vh, o, NN, FIN, FIN, D0);

    fill_csr<<<(EE + TB - 1) / TB, TB>>>(ei, ea, offs, deg, csrc, ca);

    node_agg256<<<2368, 128>>>(q, kh, vh, o, offs, deg, csrc, ca, We0, statsA, 1.f / 16.f);

    bn_apply<D0><<<(NN + 63) / 64, 256>>>(o, statsA, gamma0, beta0, xs, hh, pool, batch, 0);

    dim3 g1(4 * DIMV / BN, (NN + BM - 1) / BM);
    hgemm4<<<g1, 256>>>(hh, Wph1, bp1, q, kh, vh, o, NN, D0, D0, DIMV);

    node_agg64<<<1184, 256>>>(q, kh, vh, o, offs, deg, csrc, ca, We1, statsB, 1.f / 8.f);

    bn_apply<DIMV><<<(NN + 255) / 256, 256>>>(o, statsB, gamma1, beta1, xs, nullptr, pool,
                                              batch, D0);

    pool_div<<<(GG * OUTW + TB - 1) / TB, TB>>>(pool, cnt);
}

// round 12
// speedup vs baseline: 1.2800x; 1.1474x over previous
#include <cuda_runtime.h>
#include <cuda_fp16.h>
#include <cstdint>

#define NN   50000
#define EE   800000
#define FIN  128
#define D0   256
#define DIMV 64
#define GG   256
#define OUTW 320   // D0 + DIMV

// ---------------- scratch (device globals; no allocation) ----------------
__device__ float  g_q[NN * D0];
__device__ __half g_kh[NN * D0];
__device__ __half g_vh[NN * D0];
__device__ float  g_o[NN * D0];
__device__ __half g_xh[NN * FIN];
__device__ __half g_hh[NN * D0];
__device__ int    g_deg[NN];
__device__ int    g_offs[NN];
__device__ int    g_csrc[EE];
__device__ float  g_ca[EE];
__device__ int    g_bsum[64];
__device__ float  g_statsA[2 * D0];
__device__ float  g_statsB[2 * DIMV];
__device__ float  g_cnt[GG];
__device__ __half g_Wph0[FIN * 4 * D0];
__device__ float  g_bp0[4 * D0];
__device__ __half g_Wph1[D0 * 4 * DIMV];
__device__ float  g_bp1[4 * DIMV];

// ---------------- helpers ----------------
__device__ __forceinline__ void red_add_v4(float* ptr, float4 v) {
    asm volatile("red.global.add.v4.f32 [%0], {%1,%2,%3,%4};"
                 :: "l"(ptr), "f"(v.x), "f"(v.y), "f"(v.z), "f"(v.w) : "memory");
}
__device__ __forceinline__ uint32_t smem_u32(const void* p) {
    return (uint32_t)__cvta_generic_to_shared(p);
}
__device__ __forceinline__ void cp_async16(uint32_t dst, const void* src, int src_sz) {
    asm volatile("cp.async.cg.shared.global [%0], [%1], 16, %2;"
                 :: "r"(dst), "l"(src), "r"(src_sz));
}
__device__ __forceinline__ void cp_commit() {
    asm volatile("cp.async.commit_group;");
}
__device__ __forceinline__ void ldsm_x4(uint32_t& r0, uint32_t& r1, uint32_t& r2,
                                        uint32_t& r3, uint32_t addr) {
    asm volatile("ldmatrix.sync.aligned.m8n8.x4.shared.b16 {%0,%1,%2,%3}, [%4];"
                 : "=r"(r0), "=r"(r1), "=r"(r2), "=r"(r3) : "r"(addr));
}
__device__ __forceinline__ void ldsm_x4_t(uint32_t& r0, uint32_t& r1, uint32_t& r2,
                                          uint32_t& r3, uint32_t addr) {
    asm volatile("ldmatrix.sync.aligned.m8n8.x4.trans.shared.b16 {%0,%1,%2,%3}, [%4];"
                 : "=r"(r0), "=r"(r1), "=r"(r2), "=r"(r3) : "r"(addr));
}
__device__ __forceinline__ void mma_f16(float& c0, float& c1, float& c2, float& c3,
                                        uint32_t a0, uint32_t a1, uint32_t a2, uint32_t a3,
                                        uint32_t b0, uint32_t b1) {
    asm volatile("mma.sync.aligned.m16n8k16.row.col.f32.f16.f16.f32 "
                 "{%0,%1,%2,%3}, {%4,%5,%6,%7}, {%8,%9}, {%0,%1,%2,%3};"
                 : "+f"(c0), "+f"(c1), "+f"(c2), "+f"(c3)
                 : "r"(a0), "r"(a1), "r"(a2), "r"(a3), "r"(b0), "r"(b1));
}

// ---------------- prep: zeroing + fp16 weight packing + x conversion ---------
__global__ void prep(float* pool, float* cnt, int* deg, float* statsA, float* statsB,
                     const float* __restrict__ x, __half* xh,
                     const float* __restrict__ Wq0, const float* __restrict__ Wk0,
                     const float* __restrict__ Wv0, const float* __restrict__ Ws0,
                     const float* __restrict__ bq0, const float* __restrict__ bk0,
                     const float* __restrict__ bv0, const float* __restrict__ bs0,
                     const float* __restrict__ Wq1, const float* __restrict__ Wk1,
                     const float* __restrict__ Wv1, const float* __restrict__ Ws1,
                     const float* __restrict__ bq1, const float* __restrict__ bk1,
                     const float* __restrict__ bv1, const float* __restrict__ bs1,
                     __half* Wph0, float* bp0, __half* Wph1, float* bp1) {
    int gs = gridDim.x * blockDim.x;
    int i0 = blockIdx.x * blockDim.x + threadIdx.x;
    for (int i = i0; i < GG * OUTW; i += gs) pool[i] = 0.f;
    for (int i = i0; i < GG; i += gs) cnt[i] = 0.f;
    for (int i = i0; i < NN; i += gs) deg[i] = 0;
    for (int i = i0; i < 2 * D0; i += gs) statsA[i] = 0.f;
    for (int i = i0; i < 2 * DIMV; i += gs) statsB[i] = 0.f;
    for (int i = i0; i < NN * FIN / 2; i += gs) {
        float2 v = *(const float2*)&x[i * 2];
        *(__half2*)&xh[i * 2] = __floats2half2_rn(v.x, v.y);
    }
    for (int i = i0; i < FIN * 4 * D0; i += gs) {
        int kk = i / (4 * D0), c = i % (4 * D0);
        int sel = c / D0, cc = c % D0;
        const float* W = sel == 0 ? Wq0 : sel == 1 ? Wk0 : sel == 2 ? Wv0 : Ws0;
        Wph0[i] = __float2half_rn(W[kk * D0 + cc]);
    }
    for (int i = i0; i < 4 * D0; i += gs) {
        int sel = i / D0, cc = i % D0;
        const float* b = sel == 0 ? bq0 : sel == 1 ? bk0 : sel == 2 ? bv0 : bs0;
        bp0[i] = b[cc];
    }
    for (int i = i0; i < D0 * 4 * DIMV; i += gs) {
        int kk = i / (4 * DIMV), c = i % (4 * DIMV);
        int sel = c / DIMV, cc = c % DIMV;
        const float* W = sel == 0 ? Wq1 : sel == 1 ? Wk1 : sel == 2 ? Wv1 : Ws1;
        Wph1[i] = __float2half_rn(W[kk * DIMV + cc]);
    }
    for (int i = i0; i < 4 * DIMV; i += gs) {
        int sel = i / DIMV, cc = i % DIMV;
        const float* b = sel == 0 ? bq1 : sel == 1 ? bk1 : sel == 2 ? bv1 : bs1;
        bp1[i] = b[cc];
    }
}

// ---------------- CSR build --------------------------------------------------
__global__ void hist_count(const int* __restrict__ ei, int* deg,
                           const int* __restrict__ batch, float* cnt) {
    int i = blockIdx.x * blockDim.x + threadIdx.x;
    if (i < EE) atomicAdd(&deg[ei[EE + i]], 1);
    if (i < NN) atomicAdd(&cnt[batch[i]], 1.f);
}

// 3-phase parallel scan: per-block scan -> top scan -> add + reset deg
__global__ void scan_part(const int* __restrict__ deg, int* offs, int* bsum) {
    __shared__ int ps[1024];
    int t = threadIdx.x;
    int idx = blockIdx.x * 1024 + t;
    int d = (idx < NN) ? deg[idx] : 0;
    ps[t] = d;
    __syncthreads();
    for (int off = 1; off < 1024; off <<= 1) {
        int v = (t >= off) ? ps[t - off] : 0;
        __syncthreads();
        ps[t] += v;
        __syncthreads();
    }
    if (idx < NN) offs[idx] = ps[t] - d;   // exclusive
    if (t == 1023) bsum[blockIdx.x] = ps[1023];
}

__global__ void scan_tops(int* bsum, int nblk) {
    if (threadIdx.x == 0) {
        int run = 0;
        for (int i = 0; i < nblk; i++) {
            int v = bsum[i];
            bsum[i] = run;
            run += v;
        }
    }
}

__global__ void scan_add(int* offs, int* deg, const int* __restrict__ bsum) {
    int idx = blockIdx.x * 1024 + threadIdx.x;
    if (idx < NN) {
        offs[idx] += bsum[blockIdx.x];
        deg[idx] = 0;  // reset as fill cursor
    }
}

__global__ void fill_csr(const int* __restrict__ ei, const float* __restrict__ ea,
                         const int* __restrict__ offs, int* deg,
                         int* csrc, float* ca) {
    int e = blockIdx.x * blockDim.x + threadIdx.x;
    if (e >= EE) return;
    int dst = ei[EE + e];
    int slot = offs[dst] + atomicAdd(&deg[dst], 1);
    csrc[slot] = ei[e];
    ca[slot] = ea[e];
}

// ---------------- fp16 tensor-core GEMM, cp.async double-buffered ------------
#define BM 128
#define BN 128
#define BKH 32
#define APITCH 40
#define BPITCH 136

__global__ __launch_bounds__(256)
void hgemm4(const __half* __restrict__ A, const __half* __restrict__ Wp,
            const float* __restrict__ bp,
            float* __restrict__ Oq, __half* __restrict__ Ok,
            __half* __restrict__ Ov, float* __restrict__ Oo,
            int M, int K, int lda, int D) {
    const int Nc = 4 * D;
    __shared__ __half As[2][BM][APITCH];
    __shared__ __half Bs[2][BKH][BPITCH];

    int t = threadIdx.x;
    int lane = t & 31;
    int warp = t >> 5;
    int wm = warp >> 2;
    int wn = warp & 3;
    int g = lane >> 2;
    int t4 = lane & 3;
    int row0 = blockIdx.y * BM;
    int col0 = blockIdx.x * BN;

    float acc[4][4][4] = {};

    int a_r0 = t >> 2, a_c0 = (t & 3) * 8;
    int a_r1 = (t + 256) >> 2, a_c1 = ((t + 256) & 3) * 8;
    int b_r0 = t >> 4, b_c0 = (t & 15) * 8;
    int b_r1 = (t + 256) >> 4, b_c1 = ((t + 256) & 15) * 8;

    int a_row_l = lane & 15;
    int a_koff = (lane >> 4) * 8;
    int b_krow_l = ((lane >> 3) & 1) * 8 + (lane & 7);
    int b_noff = (lane >> 4) * 8;

    const int KT = K / BKH;

    auto load_tiles = [&](int st, int k0) {
        int gr0 = row0 + a_r0, gr1 = row0 + a_r1;
        cp_async16(smem_u32(&As[st][a_r0][a_c0]), &A[gr0 * lda + k0 + a_c0],
                   gr0 < M ? 16 : 0);
        cp_async16(smem_u32(&As[st][a_r1][a_c1]), &A[gr1 * lda + k0 + a_c1],
                   gr1 < M ? 16 : 0);
        cp_async16(smem_u32(&Bs[st][b_r0][b_c0]), &Wp[(k0 + b_r0) * Nc + col0 + b_c0], 16);
        cp_async16(smem_u32(&Bs[st][b_r1][b_c1]), &Wp[(k0 + b_r1) * Nc + col0 + b_c1], 16);
    };

    load_tiles(0, 0);
    cp_commit();

    for (int kt = 0; kt < KT; kt++) {
        int st = kt & 1;
        if (kt + 1 < KT) {
            load_tiles(st ^ 1, (kt + 1) * BKH);
            cp_commit();
            asm volatile("cp.async.wait_group 1;");
        } else {
            asm volatile("cp.async.wait_group 0;");
        }
        __syncthreads();

        #pragma unroll
        for (int ks = 0; ks < 2; ks++) {
            int kk = ks * 16;
            uint32_t af[4][4], bf[4][2];
            #pragma unroll
            for (int mt = 0; mt < 4; mt++) {
                int rb = wm * 64 + mt * 16;
                uint32_t addr = smem_u32(&As[st][rb + a_row_l][kk + a_koff]);
                ldsm_x4(af[mt][0], af[mt][1], af[mt][2], af[mt][3], addr);
            }
            #pragma unroll
            for (int p = 0; p < 2; p++) {
                int n0 = wn * 32 + p * 16;
                uint32_t addr = smem_u32(&Bs[st][kk + b_krow_l][n0 + b_noff]);
                ldsm_x4_t(bf[2 * p][0], bf[2 * p][1], bf[2 * p + 1][0], bf[2 * p + 1][1],
                          addr);
            }
            #pragma unroll
            for (int mt = 0; mt < 4; mt++)
                #pragma unroll
                for (int nt = 0; nt < 4; nt++)
                    mma_f16(acc[mt][nt][0], acc[mt][nt][1], acc[mt][nt][2], acc[mt][nt][3],
                            af[mt][0], af[mt][1], af[mt][2], af[mt][3],
                            bf[nt][0], bf[nt][1]);
        }
        __syncthreads();
    }

    #pragma unroll
    for (int nt = 0; nt < 4; nt++) {
        int cg = col0 + wn * 32 + nt * 8;
        int sel = cg / D;
        int cc = cg % D;
        int c0 = cc + 2 * t4;
        float2 bias = *(const float2*)&bp[cg + 2 * t4];
        if (sel == 1 || sel == 2) {
            __half* O = (sel == 1) ? Ok : Ov;
            #pragma unroll
            for (int mt = 0; mt < 4; mt++) {
                int r0 = row0 + wm * 64 + mt * 16 + g;
                if (r0 < M)
                    *(__half2*)&O[r0 * D + c0] =
                        __floats2half2_rn(acc[mt][nt][0] + bias.x, acc[mt][nt][1] + bias.y);
                if (r0 + 8 < M)
                    *(__half2*)&O[(r0 + 8) * D + c0] =
                        __floats2half2_rn(acc[mt][nt][2] + bias.x, acc[mt][nt][3] + bias.y);
            }
        } else {
            float* O = (sel == 0) ? Oq : Oo;
            #pragma unroll
            for (int mt = 0; mt < 4; mt++) {
                int r0 = row0 + wm * 64 + mt * 16 + g;
                if (r0 < M)
                    *(float2*)&O[r0 * D + c0] =
                        make_float2(acc[mt][nt][0] + bias.x, acc[mt][nt][1] + bias.y);
                if (r0 + 8 < M)
                    *(float2*)&O[(r0 + 8) * D + c0] =
                        make_float2(acc[mt][nt][2] + bias.x, acc[mt][nt][3] + bias.y);
            }
        }
    }
}

// ---------------- packed-dot helpers -----------------------------------------
__device__ __forceinline__ float dot_packed8(uint4 u, const float* qr) {
    float d = 0.f;
    float2 f;
    f = __half22float2(*(__half2*)&u.x); d = fmaf(qr[0], f.x, d); d = fmaf(qr[1], f.y, d);
    f = __half22float2(*(__half2*)&u.y); d = fmaf(qr[2], f.x, d); d = fmaf(qr[3], f.y, d);
    f = __half22float2(*(__half2*)&u.z); d = fmaf(qr[4], f.x, d); d = fmaf(qr[5], f.y, d);
    f = __half22float2(*(__half2*)&u.w); d = fmaf(qr[6], f.x, d); d = fmaf(qr[7], f.y, d);
    return d;
}
__device__ __forceinline__ void acc_packed8(uint4 u, float p, float* acc) {
    float2 f;
    f = __half22float2(*(__half2*)&u.x); acc[0] = fmaf(p, f.x, acc[0]); acc[1] = fmaf(p, f.y, acc[1]);
    f = __half22float2(*(__half2*)&u.y); acc[2] = fmaf(p, f.x, acc[2]); acc[3] = fmaf(p, f.y, acc[3]);
    f = __half22float2(*(__half2*)&u.z); acc[4] = fmaf(p, f.x, acc[4]); acc[5] = fmaf(p, f.y, acc[5]);
    f = __half22float2(*(__half2*)&u.w); acc[6] = fmaf(p, f.x, acc[6]); acc[7] = fmaf(p, f.y, acc[7]);
}

// ---------------- node aggregation D=256: 2-edge batch, 3-stage pipeline -----
// 192-thread blocks (6 warps). Warp per node. Depth-2 cp.async pipeline: each
// lane copies its own 16B of k/v for batch b+2 while computing batch b from
// smem. Lane reads only bytes it copied -> no syncwarp.
__global__ __launch_bounds__(192)
void node_agg256(const float* __restrict__ q, const __half* __restrict__ kh,
                 const __half* __restrict__ vh, float* __restrict__ o,
                 const int* __restrict__ offs, const int* __restrict__ deg,
                 const int* __restrict__ csrc, const float* __restrict__ ca,
                 const float* __restrict__ We, float* __restrict__ stats, float scale) {
    constexpr int D = 256;
    constexpr int C = 8;
    __shared__ __align__(16) __half kv[6][3][4][256];  // [warp][stage][row][512B]
    __shared__ float ssu[D], ssq[D];
    int t = threadIdx.x, lane = t & 31, w = t / 32;    // w: 0..5
    for (int i = t; i < D; i += 192) { ssu[i] = 0.f; ssq[i] = 0.f; }
    __syncthreads();
    int c0 = lane * C;
    float su[C] = {}, sq[C] = {};
    int wg = blockIdx.x * 6 + w, tw = gridDim.x * 6;

    uint32_t sb[3];
    sb[0] = smem_u32(&kv[w][0][0][lane * 8]);
    sb[1] = smem_u32(&kv[w][1][0][lane * 8]);
    sb[2] = smem_u32(&kv[w][2][0][lane * 8]);

    for (int n = wg; n < NN; n += tw) {
        float qr[C];
        {
            float4 a0 = *(const float4*)&q[n * D + c0];
            float4 a1 = *(const float4*)&q[n * D + c0 + 4];
            qr[0] = a0.x; qr[1] = a0.y; qr[2] = a0.z; qr[3] = a0.w;
            qr[4] = a1.x; qr[5] = a1.y; qr[6] = a1.z; qr[7] = a1.w;
        }
        float qwe = 0.f;
        #pragma unroll
        for (int i = 0; i < C; i++) qwe += qr[i] * __ldg(&We[c0 + i]);
        #pragma unroll
        for (int off = 16; off > 0; off >>= 1)
            qwe += __shfl_xor_sync(0xffffffffu, qwe, off);

        float acc[C] = {};
        float s = 0.f, pa = 0.f;
        int jb = offs[n], dg = deg[n];
        int nb = dg >> 1;   // 2-edge batches

        auto prefetch = [&](int jj, uint32_t sbase) {
            int e0 = __ldg(&csrc[jj]), e1 = __ldg(&csrc[jj + 1]);
            cp_async16(sbase + 0 * 512, &kh[e0 * D + c0], 16);
            cp_async16(sbase + 1 * 512, &kh[e1 * D + c0], 16);
            cp_async16(sbase + 2 * 512, &vh[e0 * D + c0], 16);
            cp_async16(sbase + 3 * 512, &vh[e1 * D + c0], 16);
            cp_commit();
        };

        if (nb > 0) prefetch(jb, sb[0]);
        if (nb > 1) prefetch(jb + 2, sb[1]);
        int j = jb;
        for (int b = 0; b < nb; b++) {
            if (b + 2 < nb) {
                int st2 = (b + 2) % 3;
                prefetch(j + 4, sb[st2]);
                asm volatile("cp.async.wait_group 2;");
            } else if (b + 1 < nb) {
                asm volatile("cp.async.wait_group 1;");
            } else {
                asm volatile("cp.async.wait_group 0;");
            }
            const __half* buf = &kv[w][b % 3][0][lane * 8];
            float a0 = __ldg(&ca[j]), a1 = __ldg(&ca[j + 1]);
            uint4 k0 = *(const uint4*)(buf + 0 * 256);
            uint4 k1 = *(const uint4*)(buf + 1 * 256);
            float d0 = dot_packed8(k0, qr), d1 = dot_packed8(k1, qr);
            #pragma unroll
            for (int off = 16; off > 0; off >>= 1) {
                d0 += __shfl_xor_sync(0xffffffffu, d0, off);
                d1 += __shfl_xor_sync(0xffffffffu, d1, off);
            }
            float p0 = __expf((d0 + a0 * qwe) * scale);
            float p1 = __expf((d1 + a1 * qwe) * scale);
            s += p0 + p1;
            pa = fmaf(p0, a0, pa); pa = fmaf(p1, a1, pa);
            uint4 v0 = *(const uint4*)(buf + 2 * 256);
            uint4 v1 = *(const uint4*)(buf + 3 * 256);
            acc_packed8(v0, p0, acc); acc_packed8(v1, p1, acc);
            j += 2;
        }
        if (dg & 1) {   // tail edge (direct LDG)
            int e0 = __ldg(&csrc[j]);
            float a0 = __ldg(&ca[j]);
            uint4 k0 = *(const uint4*)&kh[e0 * D + c0];
            uint4 v0 = *(const uint4*)&vh[e0 * D + c0];
            float d0 = dot_packed8(k0, qr);
            #pragma unroll
            for (int off = 16; off > 0; off >>= 1)
                d0 += __shfl_xor_sync(0xffffffffu, d0, off);
            float p0 = __expf((d0 + a0 * qwe) * scale);
            s += p0;
            pa = fmaf(p0, a0, pa);
            acc_packed8(v0, p0, acc);
        }

        float inv = 1.f / (s + 1e-16f);
        float val[C];
        float4 s0 = *(const float4*)&o[n * D + c0];
        float4 s1 = *(const float4*)&o[n * D + c0 + 4];
        float sk[8] = {s0.x, s0.y, s0.z, s0.w, s1.x, s1.y, s1.z, s1.w};
        #pragma unroll
        for (int i = 0; i < 8; i++)
            val[i] = sk[i] + (acc[i] + pa * __ldg(&We[c0 + i])) * inv;
        *(float4*)&o[n * D + c0] = make_float4(val[0], val[1], val[2], val[3]);
        *(float4*)&o[n * D + c0 + 4] = make_float4(val[4], val[5], val[6], val[7]);
        #pragma unroll
        for (int i = 0; i < C; i++) { su[i] += val[i]; sq[i] += val[i] * val[i]; }
    }

    #pragma unroll
    for (int i = 0; i < C; i++) {
        atomicAdd(&ssu[c0 + i], su[i]);
        atomicAdd(&ssq[c0 + i], sq[i]);
    }
    __syncthreads();
    for (int i = t; i < D; i += 192) {
        atomicAdd(&stats[i], ssu[i]);
        atomicAdd(&stats[D + i], ssq[i]);
    }
}

// ---------------- node aggregation D=64: direct path -------------------------
__global__ __launch_bounds__(256, 3)
void node_agg64(const float* __restrict__ q, const __half* __restrict__ kh,
                const __half* __restrict__ vh, float* __restrict__ o,
                const int* __restrict__ offs, const int* __restrict__ deg,
                const int* __restrict__ csrc, const float* __restrict__ ca,
                const float* __restrict__ We, float* __restrict__ stats, float scale) {
    constexpr int D = 64;
    constexpr int C = 2;
    __shared__ float ssu[D], ssq[D];
    int t = threadIdx.x, lane = t & 31, w = t >> 5;
    for (int i = t; i < D; i += 256) { ssu[i] = 0.f; ssq[i] = 0.f; }
    __syncthreads();
    int c0 = lane * C;
    float su[C] = {}, sq[C] = {};
    int wg = blockIdx.x * 8 + w, tw = gridDim.x * 8;

    for (int n = wg; n < NN; n += tw) {
        float qr[C];
        float2 a0v = *(const float2*)&q[n * D + c0];
        qr[0] = a0v.x; qr[1] = a0v.y;
        float qwe = qr[0] * __ldg(&We[c0]) + qr[1] * __ldg(&We[c0 + 1]);
        #pragma unroll
        for (int off = 16; off > 0; off >>= 1)
            qwe += __shfl_xor_sync(0xffffffffu, qwe, off);

        float acc[C] = {};
        float s = 0.f, pa = 0.f;
        int jb = offs[n], je = jb + deg[n];
        int j = jb;
        for (; j + 4 <= je; j += 4) {
            int e0 = __ldg(&csrc[j]),     e1 = __ldg(&csrc[j + 1]);
            int e2 = __ldg(&csrc[j + 2]), e3 = __ldg(&csrc[j + 3]);
            float a0 = __ldg(&ca[j]),     a1 = __ldg(&ca[j + 1]);
            float a2 = __ldg(&ca[j + 2]), a3 = __ldg(&ca[j + 3]);
            uint32_t k0 = *(const uint32_t*)&kh[e0 * D + c0];
            uint32_t k1 = *(const uint32_t*)&kh[e1 * D + c0];
            uint32_t k2 = *(const uint32_t*)&kh[e2 * D + c0];
            uint32_t k3 = *(const uint32_t*)&kh[e3 * D + c0];
            uint32_t v0 = *(const uint32_t*)&vh[e0 * D + c0];
            uint32_t v1 = *(const uint32_t*)&vh[e1 * D + c0];
            uint32_t v2 = *(const uint32_t*)&vh[e2 * D + c0];
            uint32_t v3 = *(const uint32_t*)&vh[e3 * D + c0];
            float d0, d1, d2, d3;
            float2 f;
            f = __half22float2(*(__half2*)&k0); d0 = qr[0] * f.x + qr[1] * f.y;
            f = __half22float2(*(__half2*)&k1); d1 = qr[0] * f.x + qr[1] * f.y;
            f = __half22float2(*(__half2*)&k2); d2 = qr[0] * f.x + qr[1] * f.y;
            f = __half22float2(*(__half2*)&k3); d3 = qr[0] * f.x + qr[1] * f.y;
            #pragma unroll
            for (int off = 16; off > 0; off >>= 1) {
                d0 += __shfl_xor_sync(0xffffffffu, d0, off);
                d1 += __shfl_xor_sync(0xffffffffu, d1, off);
                d2 += __shfl_xor_sync(0xffffffffu, d2, off);
                d3 += __shfl_xor_sync(0xffffffffu, d3, off);
            }
            float p0 = __expf((d0 + a0 * qwe) * scale);
            float p1 = __expf((d1 + a1 * qwe) * scale);
            float p2 = __expf((d2 + a2 * qwe) * scale);
            float p3 = __expf((d3 + a3 * qwe) * scale);
            s += (p0 + p1) + (p2 + p3);
            pa = fmaf(p0, a0, pa); pa = fmaf(p1, a1, pa);
            pa = fmaf(p2, a2, pa); pa = fmaf(p3, a3, pa);
            f = __half22float2(*(__half2*)&v0); acc[0] = fmaf(p0, f.x, acc[0]); acc[1] = fmaf(p0, f.y, acc[1]);
            f = __half22float2(*(__half2*)&v1); acc[0] = fmaf(p1, f.x, acc[0]); acc[1] = fmaf(p1, f.y, acc[1]);
            f = __half22float2(*(__half2*)&v2); acc[0] = fmaf(p2, f.x, acc[0]); acc[1] = fmaf(p2, f.y, acc[1]);
            f = __half22float2(*(__half2*)&v3); acc[0] = fmaf(p3, f.x, acc[0]); acc[1] = fmaf(p3, f.y, acc[1]);
        }
        for (; j < je; j++) {
            int e0 = __ldg(&csrc[j]);
            float a0 = __ldg(&ca[j]);
            uint32_t k0 = *(const uint32_t*)&kh[e0 * D + c0];
            uint32_t v0 = *(const uint32_t*)&vh[e0 * D + c0];
            float2 f = __half22float2(*(__half2*)&k0);
            float d0 = qr[0] * f.x + qr[1] * f.y;
            #pragma unroll
            for (int off = 16; off > 0; off >>= 1)
                d0 += __shfl_xor_sync(0xffffffffu, d0, off);
            float p0 = __expf((d0 + a0 * qwe) * scale);
            s += p0;
            pa = fmaf(p0, a0, pa);
            f = __half22float2(*(__half2*)&v0);
            acc[0] = fmaf(p0, f.x, acc[0]); acc[1] = fmaf(p0, f.y, acc[1]);
        }

        float inv = 1.f / (s + 1e-16f);
        float val[C];
        float2 s0 = *(const float2*)&o[n * D + c0];
        val[0] = s0.x + (acc[0] + pa * __ldg(&We[c0])) * inv;
        val[1] = s0.y + (acc[1] + pa * __ldg(&We[c0 + 1])) * inv;
        *(float2*)&o[n * D + c0] = make_float2(val[0], val[1]);
        #pragma unroll
        for (int i = 0; i < C; i++) { su[i] += val[i]; sq[i] += val[i] * val[i]; }
    }

    #pragma unroll
    for (int i = 0; i < C; i++) {
        atomicAdd(&ssu[c0 + i], su[i]);
        atomicAdd(&ssq[c0 + i], sq[i]);
    }
    __syncthreads();
    for (int i = t; i < D; i += 256) {
        atomicAdd(&stats[i], ssu[i]);
        atomicAdd(&stats[D + i], ssq[i]);
    }
}

// ---------------- batch norm apply (finalize folded in) ----------------------
template <int D>
__global__ void bn_apply(const float* __restrict__ X, const float* __restrict__ stats,
                         const float* __restrict__ gamma, const float* __restrict__ beta,
                         float* __restrict__ xs, __half* __restrict__ hh,
                         float* __restrict__ pool, const int* __restrict__ batch,
                         int col_off) {
    constexpr int CG = D / 4;
    constexpr int RL = 256 / CG;
    constexpr int CHUNK = 16;
    int t = threadIdx.x;
    int cg = t % CG, rl = t / CG;
    int r0 = blockIdx.x * (RL * CHUNK) + rl * CHUNK;
    int c4 = cg * 4;
    const float invN = 1.f / (float)NN;
    float4 suv = *(const float4*)&stats[c4];
    float4 sqv = *(const float4*)&stats[D + c4];
    float4 mu, rs;
    mu.x = suv.x * invN; mu.y = suv.y * invN; mu.z = suv.z * invN; mu.w = suv.w * invN;
    rs.x = rsqrtf(sqv.x * invN - mu.x * mu.x + 1e-5f);
    rs.y = rsqrtf(sqv.y * invN - mu.y * mu.y + 1e-5f);
    rs.z = rsqrtf(sqv.z * invN - mu.z * mu.z + 1e-5f);
    rs.w = rsqrtf(sqv.w * invN - mu.w * mu.w + 1e-5f);
    float4 gm = *(const float4*)&gamma[c4];
    float4 bt = *(const float4*)&beta[c4];
    float4 acc = make_float4(0.f, 0.f, 0.f, 0.f);
    int curb = -1;
    for (int i = 0; i < CHUNK; i++) {
        int r = r0 + i;
        if (r >= NN) break;
        int b = __ldg(&batch[r]);
        if (b != curb) {
            if (curb >= 0) red_add_v4(&pool[curb * OUTW + col_off + c4], acc);
            acc = make_float4(0.f, 0.f, 0.f, 0.f);
            curb = b;
        }
        float4 xv = *(const float4*)&X[r * D + c4];
        float4 val;
        val.x = gm.x * (xv.x - mu.x) * rs.x + bt.x;
        val.y = gm.y * (xv.y - mu.y) * rs.y + bt.y;
        val.z = gm.z * (xv.z - mu.z) * rs.z + bt.z;
        val.w = gm.w * (xv.w - mu.w) * rs.w + bt.w;
        *(float4*)&xs[r * OUTW + col_off + c4] = val;
        if (hh) {
            __half2 h0 = __floats2half2_rn(val.x, val.y);
            __half2 h1 = __floats2half2_rn(val.z, val.w);
            *(uint2*)&hh[r * D + c4] = make_uint2(*(uint32_t*)&h0, *(uint32_t*)&h1);
        }
        acc.x += val.x; acc.y += val.y; acc.z += val.z; acc.w += val.w;
    }
    if (curb >= 0) red_add_v4(&pool[curb * OUTW + col_off + c4], acc);
}

__global__ void pool_div(float* pool, const float* __restrict__ cnt) {
    int i = blockIdx.x * blockDim.x + threadIdx.x;
    if (i >= GG * OUTW) return;
    pool[i] /= fmaxf(cnt[i / OUTW], 1.f);
}

// ---------------- launch -----------------------------------------------------
extern "C" void kernel_launch(void* const* d_in, const int* in_sizes, int n_in,
                              void* d_out, int out_size) {
    const float* x     = (const float*)d_in[0];
    const int*   ei    = (const int*)  d_in[1];
    const float* ea    = (const float*)d_in[2];
    const int*   batch = (const int*)  d_in[3];
    const float* Wq0 = (const float*)d_in[4];  const float* bq0 = (const float*)d_in[5];
    const float* Wk0 = (const float*)d_in[6];  const float* bk0 = (const float*)d_in[7];
    const float* Wv0 = (const float*)d_in[8];  const float* bv0 = (const float*)d_in[9];
    const float* We0 = (const float*)d_in[10];
    const float* Ws0 = (const float*)d_in[11]; const float* bs0 = (const float*)d_in[12];
    const float* gamma0 = (const float*)d_in[13]; const float* beta0 = (const float*)d_in[14];
    const float* Wq1 = (const float*)d_in[15]; const float* bq1 = (const float*)d_in[16];
    const float* Wk1 = (const float*)d_in[17]; const float* bk1 = (const float*)d_in[18];
    const float* Wv1 = (const float*)d_in[19]; const float* bv1 = (const float*)d_in[20];
    const float* We1 = (const float*)d_in[21];
    const float* Ws1 = (const float*)d_in[22]; const float* bs1 = (const float*)d_in[23];
    const float* gamma1 = (const float*)d_in[24]; const float* beta1 = (const float*)d_in[25];

    float* out  = (float*)d_out;
    float* pool = out;
    float* xs   = out + GG * OUTW;

    float *q, *o, *statsA, *statsB, *cnt, *bp0, *bp1, *ca;
    __half *kh, *vh, *xh, *hh, *Wph0, *Wph1;
    int *deg, *offs, *csrc, *bsum;
    cudaGetSymbolAddress((void**)&q, g_q);
    cudaGetSymbolAddress((void**)&kh, g_kh);
    cudaGetSymbolAddress((void**)&vh, g_vh);
    cudaGetSymbolAddress((void**)&o, g_o);
    cudaGetSymbolAddress((void**)&xh, g_xh);
    cudaGetSymbolAddress((void**)&hh, g_hh);
    cudaGetSymbolAddress((void**)&deg, g_deg);
    cudaGetSymbolAddress((void**)&offs, g_offs);
    cudaGetSymbolAddress((void**)&csrc, g_csrc);
    cudaGetSymbolAddress((void**)&ca, g_ca);
    cudaGetSymbolAddress((void**)&bsum, g_bsum);
    cudaGetSymbolAddress((void**)&statsA, g_statsA);
    cudaGetSymbolAddress((void**)&statsB, g_statsB);
    cudaGetSymbolAddress((void**)&cnt, g_cnt);
    cudaGetSymbolAddress((void**)&Wph0, g_Wph0);
    cudaGetSymbolAddress((void**)&bp0, g_bp0);
    cudaGetSymbolAddress((void**)&Wph1, g_Wph1);
    cudaGetSymbolAddress((void**)&bp1, g_bp1);

    const int TB = 256;
    const int NBLK = (NN + 1023) / 1024;   // 49

    // 0: prep  1: hist  2: scan_part  3: gemm L0 (profiled)  4: scan_tops
    // 5: scan_add  6: fill_csr  7: agg256 ...
    prep<<<512, TB>>>(pool, cnt, deg, statsA, statsB, x, xh,
                      Wq0, Wk0, Wv0, Ws0, bq0, bk0, bv0, bs0,
                      Wq1, Wk1, Wv1, Ws1, bq1, bk1, bv1, bs1,
                      Wph0, bp0, Wph1, bp1);
    hist_count<<<(EE + TB - 1) / TB, TB>>>(ei, deg, batch, cnt);
    scan_part<<<NBLK, 1024>>>(deg, offs, bsum);

    dim3 g0(4 * D0 / BN, (NN + BM - 1) / BM);
    hgemm4<<<g0, 256>>>(xh, Wph0, bp0, q, kh, vh, o, NN, FIN, FIN, D0);

    scan_tops<<<1, 64>>>(bsum, NBLK);
    scan_add<<<NBLK, 1024>>>(offs, deg, bsum);
    fill_csr<<<(EE + TB - 1) / TB, TB>>>(ei, ea, offs, deg, csrc, ca);

    node_agg256<<<1580, 192>>>(q, kh, vh, o, offs, deg, csrc, ca, We0, statsA, 1.f / 16.f);

    bn_apply<D0><<<(NN + 63) / 64, 256>>>(o, statsA, gamma0, beta0, xs, hh, pool, batch, 0);

    dim3 g1(4 * DIMV / BN, (NN + BM - 1) / BM);
    hgemm4<<<g1, 256>>>(hh, Wph1, bp1, q, kh, vh, o, NN, D0, D0, DIMV);

    node_agg64<<<1184, 256>>>(q, kh, vh, o, offs, deg, csrc, ca, We1, statsB, 1.f / 8.f);

    bn_apply<DIMV><<<(NN + 255) / 256, 256>>>(o, statsB, gamma1, beta1, xs, nullptr, pool,
                                              batch, D0);

    pool_div<<<(GG * OUTW + TB - 1) / TB, TB>>>(pool, cnt);
}